// round 1
// baseline (speedup 1.0000x reference)
#include <cuda_runtime.h>

// Problem dims (fixed by the reference).
#define NE 32
#define NT 2048
#define NH 1024
#define NI 512
#define NK 4
#define NPAIR (NT * NK)   // 8192 (token, expert) pairs

// ---- device scratch (static; no runtime allocation) ----
__device__ int   g_count[NE];
__device__ int   g_offset[NE];
__device__ int   g_cursor[NE];
__device__ int   g_tok[NPAIR];
__device__ float g_wgt[NPAIR];
__device__ float g_h[(size_t)NPAIR * NI];   // 16 MB intermediate activations

// ---------------------------------------------------------------------------
// K0: zero output + per-expert counters
// ---------------------------------------------------------------------------
__global__ void k_zero(float* __restrict__ out) {
    int i = blockIdx.x * blockDim.x + threadIdx.x;
    if (i < NT * NH) out[i] = 0.0f;
    if (i < NE) { g_count[i] = 0; g_cursor[i] = 0; }
}

// K1: histogram of pairs per expert
__global__ void k_count(const int* __restrict__ idx) {
    int p = blockIdx.x * blockDim.x + threadIdx.x;
    if (p < NPAIR) atomicAdd(&g_count[idx[p]], 1);
}

// K2: exclusive scan over 32 experts (trivial)
__global__ void k_scan() {
    if (threadIdx.x == 0) {
        int acc = 0;
        for (int e = 0; e < NE; e++) { g_offset[e] = acc; acc += g_count[e]; }
    }
}

// K3: scatter pairs into expert-contiguous order
__global__ void k_scatter(const int* __restrict__ idx, const float* __restrict__ w) {
    int p = blockIdx.x * blockDim.x + threadIdx.x;
    if (p < NPAIR) {
        int e = idx[p];
        int pos = g_offset[e] + atomicAdd(&g_cursor[e], 1);
        g_tok[pos] = p / NK;
        g_wgt[pos] = w[p];
    }
}

// ---------------------------------------------------------------------------
// GEMM tiling
// ---------------------------------------------------------------------------
#define TM 128
#define TN 64
#define BK 16
#define APAD 4
#define BPAD 4

// GEMM1: for each expert segment, h = silu(x @ Wg^T) * (x @ Wu^T)
// Block computes a TM x TN tile of BOTH gate and up halves (shares A loads).
__global__ __launch_bounds__(256, 2)
void k_gemm1(const float* __restrict__ x, const float* __restrict__ w1) {
    const int e   = blockIdx.z;
    const int cnt = g_count[e];
    const int m0  = blockIdx.y * TM;
    if (m0 >= cnt) return;
    const int seg = g_offset[e];
    const int n0  = blockIdx.x * TN;       // gate column base; up = n0 + NI

    __shared__ __align__(16) float As[BK][TM + APAD];
    __shared__ __align__(16) float Bg[BK][TN + BPAD];
    __shared__ __align__(16) float Bu[BK][TN + BPAD];

    const int tid = threadIdx.x;
    const int tx = tid & 15;          // 0..15 -> 4 cols each
    const int ty = tid >> 4;          // 0..15 -> 8 rows each

    // A loads: 128 rows x 16 k = 512 float4 slots; 2 per thread
    const int arow0 = tid >> 2;            // 0..63
    const int arow1 = arow0 + 64;          // 64..127
    const int ac4   = tid & 3;             // float4 column within BK
    const int tok0 = (m0 + arow0 < cnt) ? g_tok[seg + m0 + arow0] : -1;
    const int tok1 = (m0 + arow1 < cnt) ? g_tok[seg + m0 + arow1] : -1;
    const float* __restrict__ xr0 = (tok0 >= 0) ? x + (size_t)tok0 * NH : x;
    const float* __restrict__ xr1 = (tok1 >= 0) ? x + (size_t)tok1 * NH : x;

    // B loads: 64 rows x 16 k = 256 float4 slots; 1 per thread (per matrix)
    const int brow = tid >> 2;             // 0..63
    const int bc4  = tid & 3;
    const float* __restrict__ w1g = w1 + ((size_t)e * (2 * NI) + n0 + brow) * NH;
    const float* __restrict__ w1u = w1 + ((size_t)e * (2 * NI) + NI + n0 + brow) * NH;

    float accG[8][4], accU[8][4];
    #pragma unroll
    for (int i = 0; i < 8; i++)
        #pragma unroll
        for (int j = 0; j < 4; j++) { accG[i][j] = 0.0f; accU[i][j] = 0.0f; }

    float4 ra0, ra1, rbg, rbu;
    const float4 zero4 = make_float4(0.f, 0.f, 0.f, 0.f);
    // prime k0 = 0
    ra0 = (tok0 >= 0) ? *(const float4*)(xr0 + ac4 * 4) : zero4;
    ra1 = (tok1 >= 0) ? *(const float4*)(xr1 + ac4 * 4) : zero4;
    rbg = *(const float4*)(w1g + bc4 * 4);
    rbu = *(const float4*)(w1u + bc4 * 4);

    for (int k0 = 0; k0 < NH; k0 += BK) {
        // stage current regs into shared
        As[ac4 * 4 + 0][arow0] = ra0.x; As[ac4 * 4 + 1][arow0] = ra0.y;
        As[ac4 * 4 + 2][arow0] = ra0.z; As[ac4 * 4 + 3][arow0] = ra0.w;
        As[ac4 * 4 + 0][arow1] = ra1.x; As[ac4 * 4 + 1][arow1] = ra1.y;
        As[ac4 * 4 + 2][arow1] = ra1.z; As[ac4 * 4 + 3][arow1] = ra1.w;
        Bg[bc4 * 4 + 0][brow] = rbg.x; Bg[bc4 * 4 + 1][brow] = rbg.y;
        Bg[bc4 * 4 + 2][brow] = rbg.z; Bg[bc4 * 4 + 3][brow] = rbg.w;
        Bu[bc4 * 4 + 0][brow] = rbu.x; Bu[bc4 * 4 + 1][brow] = rbu.y;
        Bu[bc4 * 4 + 2][brow] = rbu.z; Bu[bc4 * 4 + 3][brow] = rbu.w;
        __syncthreads();

        // prefetch next k-slab (overlaps with compute below)
        const int kn = k0 + BK;
        if (kn < NH) {
            ra0 = (tok0 >= 0) ? *(const float4*)(xr0 + kn + ac4 * 4) : zero4;
            ra1 = (tok1 >= 0) ? *(const float4*)(xr1 + kn + ac4 * 4) : zero4;
            rbg = *(const float4*)(w1g + kn + bc4 * 4);
            rbu = *(const float4*)(w1u + kn + bc4 * 4);
        }

        #pragma unroll
        for (int k = 0; k < BK; k++) {
            float a[8], bg[4], bu[4];
            *(float4*)&a[0] = *(const float4*)&As[k][ty * 8];
            *(float4*)&a[4] = *(const float4*)&As[k][ty * 8 + 4];
            *(float4*)&bg[0] = *(const float4*)&Bg[k][tx * 4];
            *(float4*)&bu[0] = *(const float4*)&Bu[k][tx * 4];
            #pragma unroll
            for (int i = 0; i < 8; i++)
                #pragma unroll
                for (int j = 0; j < 4; j++) {
                    accG[i][j] = fmaf(a[i], bg[j], accG[i][j]);
                    accU[i][j] = fmaf(a[i], bu[j], accU[i][j]);
                }
        }
        __syncthreads();
    }

    // epilogue: h = silu(gate) * up  -> g_h
    #pragma unroll
    for (int i = 0; i < 8; i++) {
        const int m = m0 + ty * 8 + i;
        if (m < cnt) {
            const size_t s = (size_t)(seg + m);
            float4 hv;
            float g0 = accG[i][0], g1 = accG[i][1], g2 = accG[i][2], g3 = accG[i][3];
            hv.x = (g0 / (1.0f + __expf(-g0))) * accU[i][0];
            hv.y = (g1 / (1.0f + __expf(-g1))) * accU[i][1];
            hv.z = (g2 / (1.0f + __expf(-g2))) * accU[i][2];
            hv.w = (g3 / (1.0f + __expf(-g3))) * accU[i][3];
            *(float4*)&g_h[s * NI + n0 + tx * 4] = hv;
        }
    }
}

// GEMM2: out[token] += w * (h @ W2^T); A rows are expert-contiguous in g_h.
__global__ __launch_bounds__(256, 2)
void k_gemm2(const float* __restrict__ w2, float* __restrict__ out) {
    const int e   = blockIdx.z;
    const int cnt = g_count[e];
    const int m0  = blockIdx.y * TM;
    if (m0 >= cnt) return;
    const int seg = g_offset[e];
    const int n0  = blockIdx.x * TN;

    __shared__ __align__(16) float As[BK][TM + APAD];
    __shared__ __align__(16) float Bs[BK][TN + BPAD];

    const int tid = threadIdx.x;
    const int tx = tid & 15;
    const int ty = tid >> 4;

    const int arow0 = tid >> 2;
    const int arow1 = arow0 + 64;
    const int ac4   = tid & 3;
    const bool v0 = (m0 + arow0 < cnt);
    const bool v1 = (m0 + arow1 < cnt);
    const float* __restrict__ hr0 = g_h + (size_t)(seg + (v0 ? m0 + arow0 : 0)) * NI;
    const float* __restrict__ hr1 = g_h + (size_t)(seg + (v1 ? m0 + arow1 : 0)) * NI;

    const int brow = tid >> 2;
    const int bc4  = tid & 3;
    const float* __restrict__ wb = w2 + ((size_t)e * NH + n0 + brow) * NI;

    float acc[8][4];
    #pragma unroll
    for (int i = 0; i < 8; i++)
        #pragma unroll
        for (int j = 0; j < 4; j++) acc[i][j] = 0.0f;

    float4 ra0, ra1, rb;
    const float4 zero4 = make_float4(0.f, 0.f, 0.f, 0.f);
    ra0 = v0 ? *(const float4*)(hr0 + ac4 * 4) : zero4;
    ra1 = v1 ? *(const float4*)(hr1 + ac4 * 4) : zero4;
    rb  = *(const float4*)(wb + bc4 * 4);

    for (int k0 = 0; k0 < NI; k0 += BK) {
        As[ac4 * 4 + 0][arow0] = ra0.x; As[ac4 * 4 + 1][arow0] = ra0.y;
        As[ac4 * 4 + 2][arow0] = ra0.z; As[ac4 * 4 + 3][arow0] = ra0.w;
        As[ac4 * 4 + 0][arow1] = ra1.x; As[ac4 * 4 + 1][arow1] = ra1.y;
        As[ac4 * 4 + 2][arow1] = ra1.z; As[ac4 * 4 + 3][arow1] = ra1.w;
        Bs[bc4 * 4 + 0][brow] = rb.x; Bs[bc4 * 4 + 1][brow] = rb.y;
        Bs[bc4 * 4 + 2][brow] = rb.z; Bs[bc4 * 4 + 3][brow] = rb.w;
        __syncthreads();

        const int kn = k0 + BK;
        if (kn < NI) {
            ra0 = v0 ? *(const float4*)(hr0 + kn + ac4 * 4) : zero4;
            ra1 = v1 ? *(const float4*)(hr1 + kn + ac4 * 4) : zero4;
            rb  = *(const float4*)(wb + kn + bc4 * 4);
        }

        #pragma unroll
        for (int k = 0; k < BK; k++) {
            float a[8], b[4];
            *(float4*)&a[0] = *(const float4*)&As[k][ty * 8];
            *(float4*)&a[4] = *(const float4*)&As[k][ty * 8 + 4];
            *(float4*)&b[0] = *(const float4*)&Bs[k][tx * 4];
            #pragma unroll
            for (int i = 0; i < 8; i++)
                #pragma unroll
                for (int j = 0; j < 4; j++)
                    acc[i][j] = fmaf(a[i], b[j], acc[i][j]);
        }
        __syncthreads();
    }

    // epilogue: weighted scatter-add to output
    #pragma unroll
    for (int i = 0; i < 8; i++) {
        const int m = m0 + ty * 8 + i;
        if (m < cnt) {
            const int s  = seg + m;
            const int t  = g_tok[s];
            const float w = g_wgt[s];
            float* op = out + (size_t)t * NH + n0 + tx * 4;
            #pragma unroll
            for (int j = 0; j < 4; j++)
                atomicAdd(op + j, w * acc[i][j]);
        }
    }
}

// ---------------------------------------------------------------------------
extern "C" void kernel_launch(void* const* d_in, const int* in_sizes, int n_in,
                              void* d_out, int out_size) {
    const float* x   = (const float*)d_in[0];   // hidden_states  [T,H]
    const int*   idx = (const int*)d_in[1];     // top_k_index    [T,K]
    const float* tw  = (const float*)d_in[2];   // top_k_weights  [T,K]
    const float* w1  = (const float*)d_in[3];   // gate_up_proj   [E,2I,H]
    const float* w2  = (const float*)d_in[4];   // down_proj      [E,H,I]
    float* out = (float*)d_out;                 // [T,H] fp32

    (void)in_sizes; (void)n_in; (void)out_size;

    k_zero<<<(NT * NH + 255) / 256, 256>>>(out);
    k_count<<<(NPAIR + 255) / 256, 256>>>(idx);
    k_scan<<<1, 32>>>();
    k_scatter<<<(NPAIR + 255) / 256, 256>>>(idx, tw);

    // worst case: all 8192 pairs on one expert -> 64 m-tiles
    k_gemm1<<<dim3(NI / TN, NPAIR / TM, NE), 256>>>(x, w1);
    k_gemm2<<<dim3(NH / TN, NPAIR / TM, NE), 256>>>(w2, out);
}

// round 3
// speedup vs baseline: 1.1726x; 1.1726x over previous
#include <cuda_runtime.h>
#include <cuda_bf16.h>
#include <cstdint>

// Problem dims (fixed by the reference).
#define NE 32
#define NT 2048
#define NH 1024
#define NI 512
#define NK 4
#define NPAIR (NT * NK)   // 8192 (token, expert) pairs
#define RS 80             // smem row stride: 32 bf16 (64B) + 16B pad -> conflict-free ldmatrix

// ---- device scratch (static; no runtime allocation) ----
__device__ int   g_count[NE];
__device__ int   g_offset[NE];
__device__ int   g_cursor[NE];
__device__ int   g_tok[NPAIR];
__device__ float g_wgt[NPAIR];
__device__ int   g_slot[NPAIR];                 // (t,k) -> slot
__device__ float g_h[(size_t)NPAIR * NI];       // 16 MB intermediate
__device__ float g_part[(size_t)NPAIR * NH];    // 32 MB unweighted partials

// ===========================================================================
// warp-mma helpers (baseline ISA — no 'a' features, compiles for sm_103)
// ===========================================================================
__device__ __forceinline__ uint32_t smem_u32(const void* p) {
    uint32_t a;
    asm("{ .reg .u64 t; cvta.to.shared.u64 t, %1; cvt.u32.u64 %0, t; }" : "=r"(a) : "l"(p));
    return a;
}
__device__ __forceinline__ void ldsm4(uint32_t* r, uint32_t a) {
    asm volatile("ldmatrix.sync.aligned.m8n8.x4.shared.b16 {%0,%1,%2,%3}, [%4];"
        : "=r"(r[0]), "=r"(r[1]), "=r"(r[2]), "=r"(r[3]) : "r"(a));
}
__device__ __forceinline__ void mma_bf16(float* d, const uint32_t* a, uint32_t b0, uint32_t b1) {
    asm volatile("mma.sync.aligned.m16n8k16.row.col.f32.bf16.bf16.f32 "
        "{%0,%1,%2,%3}, {%4,%5,%6,%7}, {%8,%9}, {%0,%1,%2,%3};"
        : "+f"(d[0]), "+f"(d[1]), "+f"(d[2]), "+f"(d[3])
        : "r"(a[0]), "r"(a[1]), "r"(a[2]), "r"(a[3]), "r"(b0), "r"(b1));
}

// 8 fp32 -> 8 bf16 hi + 8 bf16 lo (residual), stored as 16B chunk (row, cu).
__device__ __forceinline__ void cvt_store8(char* hi, char* lo, int row, int cu,
                                           float4 v0, float4 v1) {
    float f[8] = {v0.x, v0.y, v0.z, v0.w, v1.x, v1.y, v1.z, v1.w};
    unsigned hw[4], lw[4];
    #pragma unroll
    for (int j = 0; j < 4; j++) {
        float a = f[2 * j], b = f[2 * j + 1];
        __nv_bfloat16 ha = __float2bfloat16(a), hb = __float2bfloat16(b);
        float ra = a - __bfloat162float(ha), rb = b - __bfloat162float(hb);
        __nv_bfloat16 la = __float2bfloat16(ra), lb = __float2bfloat16(rb);
        hw[j] = (unsigned)__bfloat16_as_ushort(ha) | ((unsigned)__bfloat16_as_ushort(hb) << 16);
        lw[j] = (unsigned)__bfloat16_as_ushort(la) | ((unsigned)__bfloat16_as_ushort(lb) << 16);
    }
    uint32_t off = (uint32_t)(row * RS + cu * 16);
    *(uint4*)(hi + off) = make_uint4(hw[0], hw[1], hw[2], hw[3]);
    *(uint4*)(lo + off) = make_uint4(lw[0], lw[1], lw[2], lw[3]);
}

// ===========================================================================
// Setup kernels
// ===========================================================================
__global__ void k_init() {
    int i = threadIdx.x;
    if (i < NE) { g_count[i] = 0; g_cursor[i] = 0; }
}
__global__ void k_count(const int* __restrict__ idx) {
    int p = blockIdx.x * blockDim.x + threadIdx.x;
    if (p < NPAIR) atomicAdd(&g_count[idx[p]], 1);
}
__global__ void k_scan() {
    if (threadIdx.x == 0) {
        int acc = 0;
        for (int e = 0; e < NE; e++) { g_offset[e] = acc; acc += g_count[e]; }
    }
}
__global__ void k_scatter(const int* __restrict__ idx, const float* __restrict__ w) {
    int p = blockIdx.x * blockDim.x + threadIdx.x;
    if (p < NPAIR) {
        int e = idx[p];
        int pos = g_offset[e] + atomicAdd(&g_cursor[e], 1);
        g_tok[pos] = p / NK;
        g_wgt[pos] = w[p];
        g_slot[p]  = pos;
    }
}

// ===========================================================================
// GEMM1: h = silu(x @ Wg^T) * (x @ Wu^T)
// block tile M=128, N=64 (gate) + 64 (up); K chunk = 32 fp32; 32 chunks
// 8 warps: wm = wid&3 (M 32 each), wn = wid>>2 (N 32 gate + 32 up each)
// ===========================================================================
__global__ __launch_bounds__(256, 1)
void k_gemm1(const float* __restrict__ x, const float* __restrict__ w1) {
    const int e   = blockIdx.z;
    const int cnt = g_count[e];
    const int m0  = blockIdx.y * 128;
    if (m0 >= cnt) return;
    const int seg = g_offset[e];
    const int n0  = blockIdx.x * 64;

    __shared__ __align__(16) char sAh[128 * RS];
    __shared__ __align__(16) char sAl[128 * RS];
    __shared__ __align__(16) char sBh[128 * RS];   // rows 0-63 gate, 64-127 up
    __shared__ __align__(16) char sBl[128 * RS];
    __shared__ int s_tok[128];

    const int tid  = threadIdx.x;
    const int lane = tid & 31;
    const int wid  = tid >> 5;
    const int wm   = wid & 3;
    const int wn   = wid >> 2;
    const int grp  = lane >> 3, lr = lane & 7;
    const int rowoff = ((grp & 1) << 3) + lr;
    const int csel   = grp >> 1;

    if (tid < 128) s_tok[tid] = (m0 + tid < cnt) ? g_tok[seg + m0 + tid] : -1;
    __syncthreads();

    const uint32_t uAh = smem_u32(sAh), uAl = smem_u32(sAl);
    const uint32_t uBh = smem_u32(sBh), uBl = smem_u32(sBl);

    float cg[2][4][4], cup[2][4][4];
    #pragma unroll
    for (int i = 0; i < 2; i++)
        #pragma unroll
        for (int b = 0; b < 4; b++)
            #pragma unroll
            for (int q = 0; q < 4; q++) { cg[i][b][q] = 0.f; cup[i][b][q] = 0.f; }

    const float4 z4 = make_float4(0.f, 0.f, 0.f, 0.f);

    for (int c = 0; c < 32; c++) {
        const int k0 = c * 32;
        // ---- load + convert: 1024 16B units (A 512, B 512), 4/thread ----
        #pragma unroll
        for (int i = 0; i < 4; i++) {
            int u = tid + i * 256;
            if (u < 512) {
                int r = u >> 2, cu2 = u & 3;
                int tok = s_tok[r];
                float4 v0 = z4, v1 = z4;
                if (tok >= 0) {
                    const float* p = x + (size_t)tok * NH + k0 + cu2 * 8;
                    v0 = *(const float4*)p; v1 = *(const float4*)(p + 4);
                }
                cvt_store8(sAh, sAl, r, cu2, v0, v1);
            } else {
                int v = u - 512;
                int r = v >> 2, cu2 = v & 3;
                const float* p = (r < 64)
                    ? w1 + ((size_t)e * (2 * NI) + n0 + r) * NH + k0 + cu2 * 8
                    : w1 + ((size_t)e * (2 * NI) + NI + n0 + (r - 64)) * NH + k0 + cu2 * 8;
                cvt_store8(sBh, sBl, r, cu2, *(const float4*)p, *(const float4*)(p + 4));
            }
        }
        __syncthreads();

        // ---- compute: 2 k16 steps ----
        #pragma unroll
        for (int kk = 0; kk < 2; kk++) {
            const uint32_t kcoff = (uint32_t)((kk * 2 + csel) * 16);
            uint32_t ah[2][4], al[2][4];
            #pragma unroll
            for (int i = 0; i < 2; i++) {
                uint32_t off = (uint32_t)((wm * 32 + i * 16 + rowoff) * RS) + kcoff;
                ldsm4(ah[i], uAh + off);
                ldsm4(al[i], uAl + off);
            }
            #pragma unroll
            for (int t = 0; t < 2; t++) {
                {   // gate rows wn*32 + t*16
                    uint32_t off = (uint32_t)((wn * 32 + t * 16 + rowoff) * RS) + kcoff;
                    uint32_t bh[4], bl[4];
                    ldsm4(bh, uBh + off); ldsm4(bl, uBl + off);
                    #pragma unroll
                    for (int i = 0; i < 2; i++)
                        #pragma unroll
                        for (int s = 0; s < 2; s++) {
                            float* d = cg[i][t * 2 + s];
                            mma_bf16(d, ah[i], bh[s], bh[s + 2]);
                            mma_bf16(d, al[i], bh[s], bh[s + 2]);
                            mma_bf16(d, ah[i], bl[s], bl[s + 2]);
                        }
                }
                {   // up rows 64 + wn*32 + t*16
                    uint32_t off = (uint32_t)((64 + wn * 32 + t * 16 + rowoff) * RS) + kcoff;
                    uint32_t bh[4], bl[4];
                    ldsm4(bh, uBh + off); ldsm4(bl, uBl + off);
                    #pragma unroll
                    for (int i = 0; i < 2; i++)
                        #pragma unroll
                        for (int s = 0; s < 2; s++) {
                            float* d = cup[i][t * 2 + s];
                            mma_bf16(d, ah[i], bh[s], bh[s + 2]);
                            mma_bf16(d, al[i], bh[s], bh[s + 2]);
                            mma_bf16(d, ah[i], bl[s], bl[s + 2]);
                        }
                }
            }
        }
        __syncthreads();
    }

    // ---- epilogue: h = silu(gate) * up ----
    #pragma unroll
    for (int i = 0; i < 2; i++)
        #pragma unroll
        for (int h = 0; h < 2; h++) {
            int r = wm * 32 + i * 16 + h * 8 + (lane >> 2);
            int m = m0 + r;
            if (m < cnt) {
                float* dst = g_h + (size_t)(seg + m) * NI + n0 + wn * 32 + 2 * (lane & 3);
                #pragma unroll
                for (int b = 0; b < 4; b++) {
                    float g0 = cg[i][b][2 * h], g1 = cg[i][b][2 * h + 1];
                    float u0 = cup[i][b][2 * h], u1 = cup[i][b][2 * h + 1];
                    float2 hv;
                    hv.x = g0 / (1.0f + __expf(-g0)) * u0;
                    hv.y = g1 / (1.0f + __expf(-g1)) * u1;
                    *(float2*)(dst + b * 8) = hv;
                }
            }
        }
}

// ===========================================================================
// GEMM2: part = h @ W2^T   block tile M=128, N=128; K chunk 32; 16 chunks
// warps: wm = wid&3 (M 32), wn = wid>>2 (N 64 each)
// ===========================================================================
__global__ __launch_bounds__(256, 1)
void k_gemm2(const float* __restrict__ w2) {
    const int e   = blockIdx.z;
    const int cnt = g_count[e];
    const int m0  = blockIdx.y * 128;
    if (m0 >= cnt) return;
    const int seg = g_offset[e];
    const int n0  = blockIdx.x * 128;

    __shared__ __align__(16) char sAh[128 * RS];
    __shared__ __align__(16) char sAl[128 * RS];
    __shared__ __align__(16) char sBh[128 * RS];
    __shared__ __align__(16) char sBl[128 * RS];

    const int tid  = threadIdx.x;
    const int lane = tid & 31;
    const int wid  = tid >> 5;
    const int wm   = wid & 3;
    const int wn   = wid >> 2;
    const int grp  = lane >> 3, lr = lane & 7;
    const int rowoff = ((grp & 1) << 3) + lr;
    const int csel   = grp >> 1;

    const uint32_t uAh = smem_u32(sAh), uAl = smem_u32(sAl);
    const uint32_t uBh = smem_u32(sBh), uBl = smem_u32(sBl);

    float acc[2][8][4];
    #pragma unroll
    for (int i = 0; i < 2; i++)
        #pragma unroll
        for (int b = 0; b < 8; b++)
            #pragma unroll
            for (int q = 0; q < 4; q++) acc[i][b][q] = 0.f;

    const float4 z4 = make_float4(0.f, 0.f, 0.f, 0.f);

    for (int c = 0; c < 16; c++) {
        const int k0 = c * 32;
        #pragma unroll
        for (int i = 0; i < 4; i++) {
            int u = tid + i * 256;
            if (u < 512) {
                int r = u >> 2, cu2 = u & 3;
                float4 v0 = z4, v1 = z4;
                if (m0 + r < cnt) {
                    const float* p = g_h + (size_t)(seg + m0 + r) * NI + k0 + cu2 * 8;
                    v0 = *(const float4*)p; v1 = *(const float4*)(p + 4);
                }
                cvt_store8(sAh, sAl, r, cu2, v0, v1);
            } else {
                int v = u - 512;
                int r = v >> 2, cu2 = v & 3;
                const float* p = w2 + ((size_t)e * NH + n0 + r) * NI + k0 + cu2 * 8;
                cvt_store8(sBh, sBl, r, cu2, *(const float4*)p, *(const float4*)(p + 4));
            }
        }
        __syncthreads();

        #pragma unroll
        for (int kk = 0; kk < 2; kk++) {
            const uint32_t kcoff = (uint32_t)((kk * 2 + csel) * 16);
            uint32_t ah[2][4], al[2][4];
            #pragma unroll
            for (int i = 0; i < 2; i++) {
                uint32_t off = (uint32_t)((wm * 32 + i * 16 + rowoff) * RS) + kcoff;
                ldsm4(ah[i], uAh + off);
                ldsm4(al[i], uAl + off);
            }
            #pragma unroll
            for (int t = 0; t < 4; t++) {
                uint32_t off = (uint32_t)((wn * 64 + t * 16 + rowoff) * RS) + kcoff;
                uint32_t bh[4], bl[4];
                ldsm4(bh, uBh + off); ldsm4(bl, uBl + off);
                #pragma unroll
                for (int i = 0; i < 2; i++)
                    #pragma unroll
                    for (int s = 0; s < 2; s++) {
                        float* d = acc[i][t * 2 + s];
                        mma_bf16(d, ah[i], bh[s], bh[s + 2]);
                        mma_bf16(d, al[i], bh[s], bh[s + 2]);
                        mma_bf16(d, ah[i], bl[s], bl[s + 2]);
                    }
            }
        }
        __syncthreads();
    }

    #pragma unroll
    for (int i = 0; i < 2; i++)
        #pragma unroll
        for (int h = 0; h < 2; h++) {
            int r = wm * 32 + i * 16 + h * 8 + (lane >> 2);
            int m = m0 + r;
            if (m < cnt) {
                float* dst = g_part + (size_t)(seg + m) * NH + n0 + wn * 64 + 2 * (lane & 3);
                #pragma unroll
                for (int b = 0; b < 8; b++) {
                    float2 v = make_float2(acc[i][b][2 * h], acc[i][b][2 * h + 1]);
                    *(float2*)(dst + b * 8) = v;
                }
            }
        }
}

// ===========================================================================
// Reduce: out[t] = sum_k w[slot(t,k)] * part[slot(t,k)]  (deterministic order)
// ===========================================================================
__global__ void k_reduce(float* __restrict__ out) {
    const int t  = blockIdx.y;
    const int h4 = threadIdx.x;                   // 256 float4 = 1024 floats
    float4 acc = make_float4(0.f, 0.f, 0.f, 0.f);
    #pragma unroll
    for (int k = 0; k < NK; k++) {
        int s = g_slot[t * NK + k];
        float w = g_wgt[s];
        float4 v = *(const float4*)(g_part + (size_t)s * NH + h4 * 4);
        acc.x += w * v.x; acc.y += w * v.y; acc.z += w * v.z; acc.w += w * v.w;
    }
    *(float4*)(out + (size_t)t * NH + h4 * 4) = acc;
}

// ===========================================================================
extern "C" void kernel_launch(void* const* d_in, const int* in_sizes, int n_in,
                              void* d_out, int out_size) {
    const float* x   = (const float*)d_in[0];   // hidden_states  [T,H]
    const int*   idx = (const int*)d_in[1];     // top_k_index    [T,K]
    const float* tw  = (const float*)d_in[2];   // top_k_weights  [T,K]
    const float* w1  = (const float*)d_in[3];   // gate_up_proj   [E,2I,H]
    const float* w2  = (const float*)d_in[4];   // down_proj      [E,H,I]
    float* out = (float*)d_out;                 // [T,H] fp32
    (void)in_sizes; (void)n_in; (void)out_size;

    k_init<<<1, 32>>>();
    k_count<<<(NPAIR + 255) / 256, 256>>>(idx);
    k_scan<<<1, 32>>>();
    k_scatter<<<(NPAIR + 255) / 256, 256>>>(idx, tw);

    // worst case: all 8192 pairs on one expert -> 64 m-tiles
    k_gemm1<<<dim3(NI / 64, NPAIR / 128, NE), 256>>>(x, w1);
    k_gemm2<<<dim3(NH / 128, NPAIR / 128, NE), 256>>>(w2);
    k_reduce<<<dim3(1, NT), 256>>>(out);
}

// round 4
// speedup vs baseline: 1.3001x; 1.1088x over previous
#include <cuda_runtime.h>
#include <cuda_bf16.h>
#include <cstdint>

// Problem dims (fixed by the reference).
#define NE 32
#define NT 2048
#define NH 1024
#define NI 512
#define NK 4
#define NPAIR (NT * NK)        // 8192 (token, expert) pairs
#define RS 80                  // smem row stride: 32 bf16 (64B) + 16B pad (conflict-free ldsm)
#define TILE_B (128 * RS)      // one 128x32 bf16 tile in smem
#define STAGE_B (4 * TILE_B)   // Ah, Al, Bh, Bl
#define MAXTILES 128

// ---- device scratch (static; no runtime allocation) ----
__device__ int   g_count[NE];
__device__ int   g_offset[NE];
__device__ int   g_cursor[NE];
__device__ int   g_tok[NPAIR];
__device__ float g_wgt[NPAIR];
__device__ int   g_slot[NPAIR];
__device__ int   g_tile_e[MAXTILES];
__device__ int   g_tile_m0[MAXTILES];
__device__ int   g_ntiles;

__device__ __nv_bfloat16 g_w1h[(size_t)NE * 2 * NI * NH];   // 67 MB
__device__ __nv_bfloat16 g_w1l[(size_t)NE * 2 * NI * NH];   // 67 MB
__device__ __nv_bfloat16 g_w2h[(size_t)NE * NH * NI];       // 33.5 MB
__device__ __nv_bfloat16 g_w2l[(size_t)NE * NH * NI];       // 33.5 MB
__device__ __nv_bfloat16 g_xh[(size_t)NT * NH];             // 4 MB
__device__ __nv_bfloat16 g_xl[(size_t)NT * NH];             // 4 MB
__device__ __nv_bfloat16 g_hh[(size_t)NPAIR * NI];          // 8 MB
__device__ __nv_bfloat16 g_hl[(size_t)NPAIR * NI];          // 8 MB
__device__ float         g_part[(size_t)NPAIR * NH];        // 32 MB

// ===========================================================================
// asm helpers (baseline ISA only — compiles for plain sm_103)
// ===========================================================================
__device__ __forceinline__ uint32_t smem_u32(const void* p) {
    uint32_t a;
    asm("{ .reg .u64 t; cvta.to.shared.u64 t, %1; cvt.u32.u64 %0, t; }" : "=r"(a) : "l"(p));
    return a;
}
__device__ __forceinline__ void ldsm4(uint32_t* r, uint32_t a) {
    asm volatile("ldmatrix.sync.aligned.m8n8.x4.shared.b16 {%0,%1,%2,%3}, [%4];"
        : "=r"(r[0]), "=r"(r[1]), "=r"(r[2]), "=r"(r[3]) : "r"(a));
}
__device__ __forceinline__ void mma_bf16(float* d, const uint32_t* a, uint32_t b0, uint32_t b1) {
    asm volatile("mma.sync.aligned.m16n8k16.row.col.f32.bf16.bf16.f32 "
        "{%0,%1,%2,%3}, {%4,%5,%6,%7}, {%8,%9}, {%0,%1,%2,%3};"
        : "+f"(d[0]), "+f"(d[1]), "+f"(d[2]), "+f"(d[3])
        : "r"(a[0]), "r"(a[1]), "r"(a[2]), "r"(a[3]), "r"(b0), "r"(b1));
}
__device__ __forceinline__ void cp16(uint32_t dst, const void* src, int szbytes) {
    asm volatile("cp.async.cg.shared.global [%0], [%1], 16, %2;"
        :: "r"(dst), "l"(src), "r"(szbytes));
}
#define CP_COMMIT() asm volatile("cp.async.commit_group;" ::: "memory")
#define CP_WAIT(n)  asm volatile("cp.async.wait_group %0;" :: "n"(n) : "memory")

// ===========================================================================
// Setup kernels
// ===========================================================================
__global__ void k_init() {
    int i = threadIdx.x;
    if (i < NE) { g_count[i] = 0; g_cursor[i] = 0; }
}
__global__ void k_count(const int* __restrict__ idx) {
    int p = blockIdx.x * blockDim.x + threadIdx.x;
    if (p < NPAIR) atomicAdd(&g_count[idx[p]], 1);
}
__global__ void k_scan() {
    if (threadIdx.x == 0) {
        int acc = 0, nt = 0;
        for (int e = 0; e < NE; e++) {
            g_offset[e] = acc;
            for (int m0 = 0; m0 < g_count[e]; m0 += 128) {
                g_tile_e[nt] = e; g_tile_m0[nt] = m0; nt++;
            }
            acc += g_count[e];
        }
        g_ntiles = nt;
    }
}
__global__ void k_scatter(const int* __restrict__ idx, const float* __restrict__ w) {
    int p = blockIdx.x * blockDim.x + threadIdx.x;
    if (p < NPAIR) {
        int e = idx[p];
        int pos = g_offset[e] + atomicAdd(&g_cursor[e], 1);
        g_tok[pos] = p / NK;
        g_wgt[pos] = w[p];
        g_slot[p]  = pos;
    }
}

// ===========================================================================
// fp32 -> bf16 hi/lo split pre-pass.  which: 0=w1, 1=w2, 2=x
// ===========================================================================
__global__ __launch_bounds__(256) void k_cvt(const float* __restrict__ src, int n8, int which) {
    int i = blockIdx.x * blockDim.x + threadIdx.x;
    if (i >= n8) return;
    __nv_bfloat16 *hi, *lo;
    if (which == 0)      { hi = g_w1h; lo = g_w1l; }
    else if (which == 1) { hi = g_w2h; lo = g_w2l; }
    else                 { hi = g_xh;  lo = g_xl;  }
    const float4* s = (const float4*)src + 2 * (size_t)i;
    float4 v0 = s[0], v1 = s[1];
    float f[8] = {v0.x, v0.y, v0.z, v0.w, v1.x, v1.y, v1.z, v1.w};
    unsigned hw[4], lw[4];
    #pragma unroll
    for (int j = 0; j < 4; j++) {
        float a = f[2 * j], b = f[2 * j + 1];
        __nv_bfloat16 ha = __float2bfloat16(a), hb = __float2bfloat16(b);
        float ra = a - __bfloat162float(ha), rb = b - __bfloat162float(hb);
        __nv_bfloat16 la = __float2bfloat16(ra), lb = __float2bfloat16(rb);
        hw[j] = (unsigned)__bfloat16_as_ushort(ha) | ((unsigned)__bfloat16_as_ushort(hb) << 16);
        lw[j] = (unsigned)__bfloat16_as_ushort(la) | ((unsigned)__bfloat16_as_ushort(lb) << 16);
    }
    ((uint4*)hi)[i] = make_uint4(hw[0], hw[1], hw[2], hw[3]);
    ((uint4*)lo)[i] = make_uint4(lw[0], lw[1], lw[2], lw[3]);
}

// ===========================================================================
// GEMM1: h = silu(x @ Wg^T) * (x @ Wu^T); persistent over (m-tile, n-tile)
// tile M=128, N=64 gate + 64 up; K chunk 32; double-buffered cp.async
// ===========================================================================
__device__ __forceinline__ void g1_load(uint32_t sst, int k0, const int* s_tok,
                                        int e, int n0, int tid) {
    #pragma unroll
    for (int i = 0; i < 8; i++) {
        const int v = tid + (i & 1) * 256;
        const int r = v >> 2, cu = v & 3;
        uint32_t dst = sst + (uint32_t)((i >> 1) * TILE_B + r * RS + cu * 16);
        if (i < 4) {
            int tok = s_tok[r];
            const __nv_bfloat16* base = (i < 2) ? g_xh : g_xl;
            const __nv_bfloat16* src = (tok >= 0) ? base + (size_t)tok * NH + k0 + cu * 8 : base;
            cp16(dst, src, (tok >= 0) ? 16 : 0);
        } else {
            int row = (r < 64) ? (n0 + r) : (NI + n0 + (r - 64));
            const __nv_bfloat16* base = (i < 6) ? g_w1h : g_w1l;
            cp16(dst, base + ((size_t)e * 2 * NI + row) * NH + k0 + cu * 8, 16);
        }
    }
}

__device__ __forceinline__ void g1_compute(uint32_t sst, int rowoff, int csel, int wm, int wn,
                                           float cg[2][4][4], float cup[2][4][4]) {
    const uint32_t uAh = sst, uAl = sst + TILE_B, uBh = sst + 2 * TILE_B, uBl = sst + 3 * TILE_B;
    #pragma unroll
    for (int kk = 0; kk < 2; kk++) {
        const uint32_t kcoff = (uint32_t)((kk * 2 + csel) * 16);
        uint32_t ah[2][4], al[2][4];
        #pragma unroll
        for (int i = 0; i < 2; i++) {
            uint32_t off = (uint32_t)((wm * 32 + i * 16 + rowoff) * RS) + kcoff;
            ldsm4(ah[i], uAh + off);
            ldsm4(al[i], uAl + off);
        }
        #pragma unroll
        for (int t = 0; t < 2; t++) {
            {
                uint32_t off = (uint32_t)((wn * 32 + t * 16 + rowoff) * RS) + kcoff;
                uint32_t bh[4], bl[4];
                ldsm4(bh, uBh + off); ldsm4(bl, uBl + off);
                #pragma unroll
                for (int i = 0; i < 2; i++)
                    #pragma unroll
                    for (int s = 0; s < 2; s++) {
                        float* d = cg[i][t * 2 + s];
                        mma_bf16(d, ah[i], bh[s], bh[s + 2]);
                        mma_bf16(d, al[i], bh[s], bh[s + 2]);
                        mma_bf16(d, ah[i], bl[s], bl[s + 2]);
                    }
            }
            {
                uint32_t off = (uint32_t)((64 + wn * 32 + t * 16 + rowoff) * RS) + kcoff;
                uint32_t bh[4], bl[4];
                ldsm4(bh, uBh + off); ldsm4(bl, uBl + off);
                #pragma unroll
                for (int i = 0; i < 2; i++)
                    #pragma unroll
                    for (int s = 0; s < 2; s++) {
                        float* d = cup[i][t * 2 + s];
                        mma_bf16(d, ah[i], bh[s], bh[s + 2]);
                        mma_bf16(d, al[i], bh[s], bh[s + 2]);
                        mma_bf16(d, ah[i], bl[s], bl[s + 2]);
                    }
            }
        }
    }
}

__global__ __launch_bounds__(256) void k_gemm1() {
    extern __shared__ char smdyn[];
    __shared__ int s_tok[128];
    const int tid = threadIdx.x, lane = tid & 31, wid = tid >> 5;
    const int wm = wid & 3, wn = wid >> 2;
    const int grp = lane >> 3, lr = lane & 7;
    const int rowoff = ((grp & 1) << 3) + lr;
    const int csel = grp >> 1;
    const uint32_t sbase = smem_u32(smdyn);
    const int nwork = g_ntiles * 8;

    for (int w = blockIdx.x; w < nwork; w += gridDim.x) {
        const int mt = w >> 3, nt = w & 7;
        const int e = g_tile_e[mt], m0 = g_tile_m0[mt];
        const int cnt = g_count[e], seg = g_offset[e];
        const int n0 = nt * 64;

        if (tid < 128) s_tok[tid] = (m0 + tid < cnt) ? g_tok[seg + m0 + tid] : -1;
        __syncthreads();

        float cg[2][4][4], cup[2][4][4];
        #pragma unroll
        for (int i = 0; i < 2; i++)
            #pragma unroll
            for (int b = 0; b < 4; b++)
                #pragma unroll
                for (int q = 0; q < 4; q++) { cg[i][b][q] = 0.f; cup[i][b][q] = 0.f; }

        g1_load(sbase, 0, s_tok, e, n0, tid); CP_COMMIT();
        for (int c = 0; c < 32; c++) {
            if (c + 1 < 32) {
                g1_load(sbase + ((c + 1) & 1) * STAGE_B, (c + 1) * 32, s_tok, e, n0, tid);
                CP_COMMIT();
                CP_WAIT(1);
            } else {
                CP_WAIT(0);
            }
            __syncthreads();
            g1_compute(sbase + (c & 1) * STAGE_B, rowoff, csel, wm, wn, cg, cup);
            __syncthreads();
        }

        // epilogue: h = silu(gate)*up -> bf16 hi/lo
        #pragma unroll
        for (int i = 0; i < 2; i++)
            #pragma unroll
            for (int h = 0; h < 2; h++) {
                int r = wm * 32 + i * 16 + h * 8 + (lane >> 2);
                int m = m0 + r;
                if (m < cnt) {
                    size_t rowb = (size_t)(seg + m) * NI + n0 + wn * 32 + 2 * (lane & 3);
                    #pragma unroll
                    for (int b = 0; b < 4; b++) {
                        float g0 = cg[i][b][2 * h], g1 = cg[i][b][2 * h + 1];
                        float u0 = cup[i][b][2 * h], u1 = cup[i][b][2 * h + 1];
                        float h0 = g0 / (1.0f + __expf(-g0)) * u0;
                        float h1 = g1 / (1.0f + __expf(-g1)) * u1;
                        __nv_bfloat16 h0h = __float2bfloat16(h0), h1h = __float2bfloat16(h1);
                        float l0 = h0 - __bfloat162float(h0h), l1 = h1 - __bfloat162float(h1h);
                        __nv_bfloat16 h0l = __float2bfloat16(l0), h1l = __float2bfloat16(l1);
                        *(unsigned*)(g_hh + rowb + b * 8) =
                            (unsigned)__bfloat16_as_ushort(h0h) | ((unsigned)__bfloat16_as_ushort(h1h) << 16);
                        *(unsigned*)(g_hl + rowb + b * 8) =
                            (unsigned)__bfloat16_as_ushort(h0l) | ((unsigned)__bfloat16_as_ushort(h1l) << 16);
                    }
                }
            }
        __syncthreads();
    }
}

// ===========================================================================
// GEMM2: part = h @ W2^T; tile M=128, N=128; K chunk 32 (16 chunks)
// ===========================================================================
__device__ __forceinline__ void g2_load(uint32_t sst, int k0, int e, int n0,
                                        int seg, int m0, int cnt, int tid) {
    #pragma unroll
    for (int i = 0; i < 8; i++) {
        const int v = tid + (i & 1) * 256;
        const int r = v >> 2, cu = v & 3;
        uint32_t dst = sst + (uint32_t)((i >> 1) * TILE_B + r * RS + cu * 16);
        if (i < 4) {
            bool ok = (m0 + r < cnt);
            const __nv_bfloat16* base = (i < 2) ? g_hh : g_hl;
            const __nv_bfloat16* src = ok ? base + (size_t)(seg + m0 + r) * NI + k0 + cu * 8 : base;
            cp16(dst, src, ok ? 16 : 0);
        } else {
            const __nv_bfloat16* base = (i < 6) ? g_w2h : g_w2l;
            cp16(dst, base + ((size_t)e * NH + n0 + r) * NI + k0 + cu * 8, 16);
        }
    }
}

__global__ __launch_bounds__(256) void k_gemm2() {
    extern __shared__ char smdyn[];
    const int tid = threadIdx.x, lane = tid & 31, wid = tid >> 5;
    const int wm = wid & 3, wn = wid >> 2;
    const int grp = lane >> 3, lr = lane & 7;
    const int rowoff = ((grp & 1) << 3) + lr;
    const int csel = grp >> 1;
    const uint32_t sbase = smem_u32(smdyn);
    const int nwork = g_ntiles * 8;

    for (int w = blockIdx.x; w < nwork; w += gridDim.x) {
        const int mt = w >> 3, nt = w & 7;
        const int e = g_tile_e[mt], m0 = g_tile_m0[mt];
        const int cnt = g_count[e], seg = g_offset[e];
        const int n0 = nt * 128;

        float acc[2][8][4];
        #pragma unroll
        for (int i = 0; i < 2; i++)
            #pragma unroll
            for (int b = 0; b < 8; b++)
                #pragma unroll
                for (int q = 0; q < 4; q++) acc[i][b][q] = 0.f;

        g2_load(sbase, 0, e, n0, seg, m0, cnt, tid); CP_COMMIT();
        for (int c = 0; c < 16; c++) {
            if (c + 1 < 16) {
                g2_load(sbase + ((c + 1) & 1) * STAGE_B, (c + 1) * 32, e, n0, seg, m0, cnt, tid);
                CP_COMMIT();
                CP_WAIT(1);
            } else {
                CP_WAIT(0);
            }
            __syncthreads();
            {
                const uint32_t sst = sbase + (c & 1) * STAGE_B;
                const uint32_t uAh = sst, uAl = sst + TILE_B, uBh = sst + 2 * TILE_B, uBl = sst + 3 * TILE_B;
                #pragma unroll
                for (int kk = 0; kk < 2; kk++) {
                    const uint32_t kcoff = (uint32_t)((kk * 2 + csel) * 16);
                    uint32_t ah[2][4], al[2][4];
                    #pragma unroll
                    for (int i = 0; i < 2; i++) {
                        uint32_t off = (uint32_t)((wm * 32 + i * 16 + rowoff) * RS) + kcoff;
                        ldsm4(ah[i], uAh + off);
                        ldsm4(al[i], uAl + off);
                    }
                    #pragma unroll
                    for (int t = 0; t < 4; t++) {
                        uint32_t off = (uint32_t)((wn * 64 + t * 16 + rowoff) * RS) + kcoff;
                        uint32_t bh[4], bl[4];
                        ldsm4(bh, uBh + off); ldsm4(bl, uBl + off);
                        #pragma unroll
                        for (int i = 0; i < 2; i++)
                            #pragma unroll
                            for (int s = 0; s < 2; s++) {
                                float* d = acc[i][t * 2 + s];
                                mma_bf16(d, ah[i], bh[s], bh[s + 2]);
                                mma_bf16(d, al[i], bh[s], bh[s + 2]);
                                mma_bf16(d, ah[i], bl[s], bl[s + 2]);
                            }
                    }
                }
            }
            __syncthreads();
        }

        #pragma unroll
        for (int i = 0; i < 2; i++)
            #pragma unroll
            for (int h = 0; h < 2; h++) {
                int r = wm * 32 + i * 16 + h * 8 + (lane >> 2);
                int m = m0 + r;
                if (m < cnt) {
                    float* dst = g_part + (size_t)(seg + m) * NH + n0 + wn * 64 + 2 * (lane & 3);
                    #pragma unroll
                    for (int b = 0; b < 8; b++)
                        *(float2*)(dst + b * 8) = make_float2(acc[i][b][2 * h], acc[i][b][2 * h + 1]);
                }
            }
    }
}

// ===========================================================================
// Reduce: out[t] = sum_k w[slot(t,k)] * part[slot(t,k)]  (deterministic order)
// ===========================================================================
__global__ void k_reduce(float* __restrict__ out) {
    const int t  = blockIdx.y;
    const int h4 = threadIdx.x;
    float4 acc = make_float4(0.f, 0.f, 0.f, 0.f);
    #pragma unroll
    for (int k = 0; k < NK; k++) {
        int s = g_slot[t * NK + k];
        float w = g_wgt[s];
        float4 v = *(const float4*)(g_part + (size_t)s * NH + h4 * 4);
        acc.x += w * v.x; acc.y += w * v.y; acc.z += w * v.z; acc.w += w * v.w;
    }
    *(float4*)(out + (size_t)t * NH + h4 * 4) = acc;
}

// ===========================================================================
extern "C" void kernel_launch(void* const* d_in, const int* in_sizes, int n_in,
                              void* d_out, int out_size) {
    const float* x   = (const float*)d_in[0];   // hidden_states  [T,H]
    const int*   idx = (const int*)d_in[1];     // top_k_index    [T,K]
    const float* tw  = (const float*)d_in[2];   // top_k_weights  [T,K]
    const float* w1  = (const float*)d_in[3];   // gate_up_proj   [E,2I,H]
    const float* w2  = (const float*)d_in[4];   // down_proj      [E,H,I]
    float* out = (float*)d_out;                 // [T,H] fp32
    (void)in_sizes; (void)n_in; (void)out_size;

    cudaFuncSetAttribute(k_gemm1, cudaFuncAttributeMaxDynamicSharedMemorySize, 2 * STAGE_B);
    cudaFuncSetAttribute(k_gemm2, cudaFuncAttributeMaxDynamicSharedMemorySize, 2 * STAGE_B);

    k_init<<<1, 32>>>();
    k_count<<<(NPAIR + 255) / 256, 256>>>(idx);
    k_scan<<<1, 32>>>();
    k_scatter<<<(NPAIR + 255) / 256, 256>>>(idx, tw);

    // pre-split fp32 -> bf16 hi/lo
    k_cvt<<<(NE * 2 * NI * NH / 8 + 255) / 256, 256>>>(w1, NE * 2 * NI * NH / 8, 0);
    k_cvt<<<(NE * NH * NI / 8 + 255) / 256, 256>>>(w2, NE * NH * NI / 8, 1);
    k_cvt<<<(NT * NH / 8 + 255) / 256, 256>>>(x, NT * NH / 8, 2);

    k_gemm1<<<592, 256, 2 * STAGE_B>>>();
    k_gemm2<<<592, 256, 2 * STAGE_B>>>();
    k_reduce<<<dim3(1, NT), 256>>>(out);
}

// round 5
// speedup vs baseline: 2.6944x; 2.0724x over previous
#include <cuda_runtime.h>
#include <cuda_fp16.h>
#include <cstdint>

// Problem dims (fixed by the reference).
#define NE 32
#define NT 2048
#define NH 1024
#define NI 512
#define NK 4
#define NPAIR (NT * NK)        // 8192 (token, expert) pairs
#define RS 80                  // smem row stride: 32 fp16 (64B) + 16B pad (conflict-free ldsm)
#define TILE_B (128 * RS)      // one 128x32 fp16 tile in smem
#define STAGE_B (3 * TILE_B)   // Ah, Al, Bh
#define NSTAGE 3
#define MAXTILES 128

// ---- device scratch (static; no runtime allocation) ----
__device__ int   g_count[NE];
__device__ int   g_offset[NE];
__device__ int   g_cursor[NE];
__device__ int   g_tok[NPAIR];
__device__ float g_wgt[NPAIR];
__device__ int   g_slot[NPAIR];
__device__ int   g_tile_e[MAXTILES];
__device__ int   g_tile_m0[MAXTILES];
__device__ int   g_ntiles;

__device__ __half g_w1h[(size_t)NE * 2 * NI * NH];   // 67 MB
__device__ __half g_w2h[(size_t)NE * NH * NI];       // 33.5 MB
__device__ __half g_xh[(size_t)NT * NH];             // 4 MB
__device__ __half g_xl[(size_t)NT * NH];             // 4 MB
__device__ __half g_hh[(size_t)NPAIR * NI];          // 8 MB
__device__ __half g_hl[(size_t)NPAIR * NI];          // 8 MB
__device__ float  g_part[(size_t)NPAIR * NH];        // 32 MB

// ===========================================================================
// asm helpers (baseline ISA only — compiles for plain sm_103)
// ===========================================================================
__device__ __forceinline__ uint32_t smem_u32(const void* p) {
    uint32_t a;
    asm("{ .reg .u64 t; cvta.to.shared.u64 t, %1; cvt.u32.u64 %0, t; }" : "=r"(a) : "l"(p));
    return a;
}
__device__ __forceinline__ void ldsm4(uint32_t* r, uint32_t a) {
    asm volatile("ldmatrix.sync.aligned.m8n8.x4.shared.b16 {%0,%1,%2,%3}, [%4];"
        : "=r"(r[0]), "=r"(r[1]), "=r"(r[2]), "=r"(r[3]) : "r"(a));
}
__device__ __forceinline__ void mma_fp16(float* d, const uint32_t* a, uint32_t b0, uint32_t b1) {
    asm volatile("mma.sync.aligned.m16n8k16.row.col.f32.f16.f16.f32 "
        "{%0,%1,%2,%3}, {%4,%5,%6,%7}, {%8,%9}, {%0,%1,%2,%3};"
        : "+f"(d[0]), "+f"(d[1]), "+f"(d[2]), "+f"(d[3])
        : "r"(a[0]), "r"(a[1]), "r"(a[2]), "r"(a[3]), "r"(b0), "r"(b1));
}
__device__ __forceinline__ void cp16(uint32_t dst, const void* src, int szbytes) {
    asm volatile("cp.async.cg.shared.global [%0], [%1], 16, %2;"
        :: "r"(dst), "l"(src), "r"(szbytes));
}
#define CP_COMMIT() asm volatile("cp.async.commit_group;" ::: "memory")
#define CP_WAIT(n)  asm volatile("cp.async.wait_group %0;" :: "n"(n) : "memory")

// ===========================================================================
// Setup kernels
// ===========================================================================
__global__ void k_init() {
    int i = threadIdx.x;
    if (i < NE) { g_count[i] = 0; g_cursor[i] = 0; }
}
__global__ void k_count(const int* __restrict__ idx) {
    int p = blockIdx.x * blockDim.x + threadIdx.x;
    if (p < NPAIR) atomicAdd(&g_count[idx[p]], 1);
}
__global__ void k_scan() {
    if (threadIdx.x == 0) {
        int acc = 0, nt = 0;
        for (int e = 0; e < NE; e++) {
            g_offset[e] = acc;
            for (int m0 = 0; m0 < g_count[e]; m0 += 128) {
                g_tile_e[nt] = e; g_tile_m0[nt] = m0; nt++;
            }
            acc += g_count[e];
        }
        g_ntiles = nt;
    }
}
__global__ void k_scatter(const int* __restrict__ idx, const float* __restrict__ w) {
    int p = blockIdx.x * blockDim.x + threadIdx.x;
    if (p < NPAIR) {
        int e = idx[p];
        int pos = g_offset[e] + atomicAdd(&g_cursor[e], 1);
        g_tok[pos] = p / NK;
        g_wgt[pos] = w[p];
        g_slot[p]  = pos;
    }
}

// ===========================================================================
// Convert pre-passes
// ===========================================================================
// fp32 -> fp16 (round only).  which: 0 = w1, 1 = w2
__global__ __launch_bounds__(256) void k_cvt_hi(const float* __restrict__ src, int n8, int which) {
    int i = blockIdx.x * blockDim.x + threadIdx.x;
    if (i >= n8) return;
    __half* hi = (which == 0) ? g_w1h : g_w2h;
    const float4* s = (const float4*)src + 2 * (size_t)i;
    float4 v0 = s[0], v1 = s[1];
    float f[8] = {v0.x, v0.y, v0.z, v0.w, v1.x, v1.y, v1.z, v1.w};
    unsigned hw[4];
    #pragma unroll
    for (int j = 0; j < 4; j++) {
        __half a = __float2half(f[2 * j]), b = __float2half(f[2 * j + 1]);
        hw[j] = (unsigned)__half_as_ushort(a) | ((unsigned)__half_as_ushort(b) << 16);
    }
    ((uint4*)hi)[i] = make_uint4(hw[0], hw[1], hw[2], hw[3]);
}
// fp32 -> fp16 hi + fp16 lo residual (for x).
__global__ __launch_bounds__(256) void k_cvt_x(const float* __restrict__ src, int n8) {
    int i = blockIdx.x * blockDim.x + threadIdx.x;
    if (i >= n8) return;
    const float4* s = (const float4*)src + 2 * (size_t)i;
    float4 v0 = s[0], v1 = s[1];
    float f[8] = {v0.x, v0.y, v0.z, v0.w, v1.x, v1.y, v1.z, v1.w};
    unsigned hw[4], lw[4];
    #pragma unroll
    for (int j = 0; j < 4; j++) {
        float a = f[2 * j], b = f[2 * j + 1];
        __half ha = __float2half(a), hb = __float2half(b);
        __half la = __float2half(a - __half2float(ha));
        __half lb = __float2half(b - __half2float(hb));
        hw[j] = (unsigned)__half_as_ushort(ha) | ((unsigned)__half_as_ushort(hb) << 16);
        lw[j] = (unsigned)__half_as_ushort(la) | ((unsigned)__half_as_ushort(lb) << 16);
    }
    ((uint4*)g_xh)[i] = make_uint4(hw[0], hw[1], hw[2], hw[3]);
    ((uint4*)g_xl)[i] = make_uint4(lw[0], lw[1], lw[2], lw[3]);
}

// ===========================================================================
// GEMM1: h = silu(x @ Wg^T) * (x @ Wu^T); persistent over (m-tile, n-tile)
// tile M=128, N=64 gate + 64 up; K chunk 32; 3-stage cp.async pipeline
// per stage: Ah(+0), Al(+TILE_B), Bh(+2*TILE_B)
// ===========================================================================
__device__ __forceinline__ void g1_load(uint32_t sst, int k0, const int* s_tok,
                                        int e, int n0, int tid) {
    #pragma unroll
    for (int i = 0; i < 6; i++) {
        const int v = tid + (i & 1) * 256;          // 0..511 within tile
        const int r = v >> 2, cu = v & 3;
        uint32_t dst = sst + (uint32_t)((i >> 1) * TILE_B + r * RS + cu * 16);
        if (i < 2) {                                 // Ah
            int tok = s_tok[r];
            const __half* src = (tok >= 0) ? g_xh + (size_t)tok * NH + k0 + cu * 8 : g_xh;
            cp16(dst, src, (tok >= 0) ? 16 : 0);
        } else if (i < 4) {                          // Al
            int tok = s_tok[r];
            const __half* src = (tok >= 0) ? g_xl + (size_t)tok * NH + k0 + cu * 8 : g_xl;
            cp16(dst, src, (tok >= 0) ? 16 : 0);
        } else {                                     // Bh: gate rows 0-63, up rows 64-127
            int row = (r < 64) ? (n0 + r) : (NI + n0 + (r - 64));
            cp16(dst, g_w1h + ((size_t)e * 2 * NI + row) * NH + k0 + cu * 8, 16);
        }
    }
}

__device__ __forceinline__ void g1_compute(uint32_t sst, int rowoff, int csel, int wm, int wn,
                                           float cg[2][4][4], float cup[2][4][4]) {
    const uint32_t uAh = sst, uAl = sst + TILE_B, uBh = sst + 2 * TILE_B;
    #pragma unroll
    for (int kk = 0; kk < 2; kk++) {
        const uint32_t kcoff = (uint32_t)((kk * 2 + csel) * 16);
        uint32_t ah[2][4], al[2][4];
        #pragma unroll
        for (int i = 0; i < 2; i++) {
            uint32_t off = (uint32_t)((wm * 32 + i * 16 + rowoff) * RS) + kcoff;
            ldsm4(ah[i], uAh + off);
            ldsm4(al[i], uAl + off);
        }
        #pragma unroll
        for (int t = 0; t < 2; t++) {
            {   // gate rows wn*32 + t*16
                uint32_t off = (uint32_t)((wn * 32 + t * 16 + rowoff) * RS) + kcoff;
                uint32_t bh[4];
                ldsm4(bh, uBh + off);
                #pragma unroll
                for (int i = 0; i < 2; i++)
                    #pragma unroll
                    for (int s = 0; s < 2; s++) {
                        float* d = cg[i][t * 2 + s];
                        mma_fp16(d, ah[i], bh[s], bh[s + 2]);
                        mma_fp16(d, al[i], bh[s], bh[s + 2]);
                    }
            }
            {   // up rows 64 + wn*32 + t*16
                uint32_t off = (uint32_t)((64 + wn * 32 + t * 16 + rowoff) * RS) + kcoff;
                uint32_t bh[4];
                ldsm4(bh, uBh + off);
                #pragma unroll
                for (int i = 0; i < 2; i++)
                    #pragma unroll
                    for (int s = 0; s < 2; s++) {
                        float* d = cup[i][t * 2 + s];
                        mma_fp16(d, ah[i], bh[s], bh[s + 2]);
                        mma_fp16(d, al[i], bh[s], bh[s + 2]);
                    }
            }
        }
    }
}

__global__ __launch_bounds__(256) void k_gemm1() {
    extern __shared__ char smdyn[];
    __shared__ int s_tok[128];
    const int tid = threadIdx.x, lane = tid & 31, wid = tid >> 5;
    const int wm = wid & 3, wn = wid >> 2;
    const int grp = lane >> 3, lr = lane & 7;
    const int rowoff = ((grp & 1) << 3) + lr;
    const int csel = grp >> 1;
    const uint32_t sbase = smem_u32(smdyn);
    const int nwork = g_ntiles * 8;

    for (int w = blockIdx.x; w < nwork; w += gridDim.x) {
        const int mt = w >> 3, nt = w & 7;
        const int e = g_tile_e[mt], m0 = g_tile_m0[mt];
        const int cnt = g_count[e], seg = g_offset[e];
        const int n0 = nt * 64;

        if (tid < 128) s_tok[tid] = (m0 + tid < cnt) ? g_tok[seg + m0 + tid] : -1;
        __syncthreads();

        float cg[2][4][4], cup[2][4][4];
        #pragma unroll
        for (int i = 0; i < 2; i++)
            #pragma unroll
            for (int b = 0; b < 4; b++)
                #pragma unroll
                for (int q = 0; q < 4; q++) { cg[i][b][q] = 0.f; cup[i][b][q] = 0.f; }

        g1_load(sbase + 0 * STAGE_B, 0,  s_tok, e, n0, tid); CP_COMMIT();
        g1_load(sbase + 1 * STAGE_B, 32, s_tok, e, n0, tid); CP_COMMIT();
        #define G1_CHUNKS 32
        for (int c = 0; c < G1_CHUNKS; c++) {
            if (c + 2 < G1_CHUNKS) {
                g1_load(sbase + ((c + 2) % NSTAGE) * STAGE_B, (c + 2) * 32, s_tok, e, n0, tid);
                CP_COMMIT();
                CP_WAIT(2);
            } else if (c + 2 == G1_CHUNKS) {
                CP_WAIT(1);
            } else {
                CP_WAIT(0);
            }
            __syncthreads();
            g1_compute(sbase + (c % NSTAGE) * STAGE_B, rowoff, csel, wm, wn, cg, cup);
            __syncthreads();
        }

        // epilogue: h = silu(gate)*up -> fp16 hi/lo
        #pragma unroll
        for (int i = 0; i < 2; i++)
            #pragma unroll
            for (int h = 0; h < 2; h++) {
                int r = wm * 32 + i * 16 + h * 8 + (lane >> 2);
                int m = m0 + r;
                if (m < cnt) {
                    size_t rowb = (size_t)(seg + m) * NI + n0 + wn * 32 + 2 * (lane & 3);
                    #pragma unroll
                    for (int b = 0; b < 4; b++) {
                        float g0 = cg[i][b][2 * h], g1 = cg[i][b][2 * h + 1];
                        float u0 = cup[i][b][2 * h], u1 = cup[i][b][2 * h + 1];
                        float h0 = g0 / (1.0f + __expf(-g0)) * u0;
                        float h1 = g1 / (1.0f + __expf(-g1)) * u1;
                        __half h0h = __float2half(h0), h1h = __float2half(h1);
                        __half h0l = __float2half(h0 - __half2float(h0h));
                        __half h1l = __float2half(h1 - __half2float(h1h));
                        *(unsigned*)(g_hh + rowb + b * 8) =
                            (unsigned)__half_as_ushort(h0h) | ((unsigned)__half_as_ushort(h1h) << 16);
                        *(unsigned*)(g_hl + rowb + b * 8) =
                            (unsigned)__half_as_ushort(h0l) | ((unsigned)__half_as_ushort(h1l) << 16);
                    }
                }
            }
        __syncthreads();
    }
}

// ===========================================================================
// GEMM2: part = h @ W2^T; tile M=128, N=128; K chunk 32 (16 chunks)
// ===========================================================================
__device__ __forceinline__ void g2_load(uint32_t sst, int k0, int e, int n0,
                                        int seg, int m0, int cnt, int tid) {
    #pragma unroll
    for (int i = 0; i < 6; i++) {
        const int v = tid + (i & 1) * 256;
        const int r = v >> 2, cu = v & 3;
        uint32_t dst = sst + (uint32_t)((i >> 1) * TILE_B + r * RS + cu * 16);
        if (i < 2) {
            bool ok = (m0 + r < cnt);
            const __half* src = ok ? g_hh + (size_t)(seg + m0 + r) * NI + k0 + cu * 8 : g_hh;
            cp16(dst, src, ok ? 16 : 0);
        } else if (i < 4) {
            bool ok = (m0 + r < cnt);
            const __half* src = ok ? g_hl + (size_t)(seg + m0 + r) * NI + k0 + cu * 8 : g_hl;
            cp16(dst, src, ok ? 16 : 0);
        } else {
            cp16(dst, g_w2h + ((size_t)e * NH + n0 + r) * NI + k0 + cu * 8, 16);
        }
    }
}

__global__ __launch_bounds__(256) void k_gemm2() {
    extern __shared__ char smdyn[];
    const int tid = threadIdx.x, lane = tid & 31, wid = tid >> 5;
    const int wm = wid & 3, wn = wid >> 2;
    const int grp = lane >> 3, lr = lane & 7;
    const int rowoff = ((grp & 1) << 3) + lr;
    const int csel = grp >> 1;
    const uint32_t sbase = smem_u32(smdyn);
    const int nwork = g_ntiles * 8;

    for (int w = blockIdx.x; w < nwork; w += gridDim.x) {
        const int mt = w >> 3, nt = w & 7;
        const int e = g_tile_e[mt], m0 = g_tile_m0[mt];
        const int cnt = g_count[e], seg = g_offset[e];
        const int n0 = nt * 128;

        float acc[2][8][4];
        #pragma unroll
        for (int i = 0; i < 2; i++)
            #pragma unroll
            for (int b = 0; b < 8; b++)
                #pragma unroll
                for (int q = 0; q < 4; q++) acc[i][b][q] = 0.f;

        g2_load(sbase + 0 * STAGE_B, 0,  e, n0, seg, m0, cnt, tid); CP_COMMIT();
        g2_load(sbase + 1 * STAGE_B, 32, e, n0, seg, m0, cnt, tid); CP_COMMIT();
        #define G2_CHUNKS 16
        for (int c = 0; c < G2_CHUNKS; c++) {
            if (c + 2 < G2_CHUNKS) {
                g2_load(sbase + ((c + 2) % NSTAGE) * STAGE_B, (c + 2) * 32, e, n0, seg, m0, cnt, tid);
                CP_COMMIT();
                CP_WAIT(2);
            } else if (c + 2 == G2_CHUNKS) {
                CP_WAIT(1);
            } else {
                CP_WAIT(0);
            }
            __syncthreads();
            {
                const uint32_t sst = sbase + (c % NSTAGE) * STAGE_B;
                const uint32_t uAh = sst, uAl = sst + TILE_B, uBh = sst + 2 * TILE_B;
                #pragma unroll
                for (int kk = 0; kk < 2; kk++) {
                    const uint32_t kcoff = (uint32_t)((kk * 2 + csel) * 16);
                    uint32_t ah[2][4], al[2][4];
                    #pragma unroll
                    for (int i = 0; i < 2; i++) {
                        uint32_t off = (uint32_t)((wm * 32 + i * 16 + rowoff) * RS) + kcoff;
                        ldsm4(ah[i], uAh + off);
                        ldsm4(al[i], uAl + off);
                    }
                    #pragma unroll
                    for (int t = 0; t < 4; t++) {
                        uint32_t off = (uint32_t)((wn * 64 + t * 16 + rowoff) * RS) + kcoff;
                        uint32_t bh[4];
                        ldsm4(bh, uBh + off);
                        #pragma unroll
                        for (int i = 0; i < 2; i++)
                            #pragma unroll
                            for (int s = 0; s < 2; s++) {
                                float* d = acc[i][t * 2 + s];
                                mma_fp16(d, ah[i], bh[s], bh[s + 2]);
                                mma_fp16(d, al[i], bh[s], bh[s + 2]);
                            }
                    }
                }
            }
            __syncthreads();
        }

        #pragma unroll
        for (int i = 0; i < 2; i++)
            #pragma unroll
            for (int h = 0; h < 2; h++) {
                int r = wm * 32 + i * 16 + h * 8 + (lane >> 2);
                int m = m0 + r;
                if (m < cnt) {
                    float* dst = g_part + (size_t)(seg + m) * NH + n0 + wn * 64 + 2 * (lane & 3);
                    #pragma unroll
                    for (int b = 0; b < 8; b++)
                        *(float2*)(dst + b * 8) = make_float2(acc[i][b][2 * h], acc[i][b][2 * h + 1]);
                }
            }
    }
}

// ===========================================================================
// Reduce: out[t] = sum_k w[slot(t,k)] * part[slot(t,k)]  (deterministic order)
// ===========================================================================
__global__ void k_reduce(float* __restrict__ out) {
    const int t  = blockIdx.y;
    const int h4 = threadIdx.x;
    float4 acc = make_float4(0.f, 0.f, 0.f, 0.f);
    #pragma unroll
    for (int k = 0; k < NK; k++) {
        int s = g_slot[t * NK + k];
        float w = g_wgt[s];
        float4 v = *(const float4*)(g_part + (size_t)s * NH + h4 * 4);
        acc.x += w * v.x; acc.y += w * v.y; acc.z += w * v.z; acc.w += w * v.w;
    }
    *(float4*)(out + (size_t)t * NH + h4 * 4) = acc;
}

// ===========================================================================
extern "C" void kernel_launch(void* const* d_in, const int* in_sizes, int n_in,
                              void* d_out, int out_size) {
    const float* x   = (const float*)d_in[0];   // hidden_states  [T,H]
    const int*   idx = (const int*)d_in[1];     // top_k_index    [T,K]
    const float* tw  = (const float*)d_in[2];   // top_k_weights  [T,K]
    const float* w1  = (const float*)d_in[3];   // gate_up_proj   [E,2I,H]
    const float* w2  = (const float*)d_in[4];   // down_proj      [E,H,I]
    float* out = (float*)d_out;                 // [T,H] fp32
    (void)in_sizes; (void)n_in; (void)out_size;

    cudaFuncSetAttribute(k_gemm1, cudaFuncAttributeMaxDynamicSharedMemorySize, NSTAGE * STAGE_B);
    cudaFuncSetAttribute(k_gemm2, cudaFuncAttributeMaxDynamicSharedMemorySize, NSTAGE * STAGE_B);

    k_init<<<1, 32>>>();
    k_count<<<(NPAIR + 255) / 256, 256>>>(idx);
    k_scan<<<1, 32>>>();
    k_scatter<<<(NPAIR + 255) / 256, 256>>>(idx, tw);

    // convert weights to fp16 (round), x to fp16 hi/lo
    k_cvt_hi<<<(NE * 2 * NI * NH / 8 + 255) / 256, 256>>>(w1, NE * 2 * NI * NH / 8, 0);
    k_cvt_hi<<<(NE * NH * NI / 8 + 255) / 256, 256>>>(w2, NE * NH * NI / 8, 1);
    k_cvt_x<<<(NT * NH / 8 + 255) / 256, 256>>>(x, NT * NH / 8);

    k_gemm1<<<592, 256, NSTAGE * STAGE_B>>>();
    k_gemm2<<<592, 256, NSTAGE * STAGE_B>>>();
    k_reduce<<<dim3(1, NT), 256>>>(out);
}

// round 9
// speedup vs baseline: 3.3041x; 1.2263x over previous
#include <cuda_runtime.h>
#include <cuda_fp16.h>
#include <cstdint>

// Problem dims (fixed by the reference).
#define NE 32
#define NT 2048
#define NH 1024
#define NI 512
#define NK 4
#define NPAIR (NT * NK)        // 8192 (token, expert) pairs
#define RS 80                  // smem row stride: 32 fp16 (64B) + 16B pad (conflict-free ldsm)
#define TILE_B (128 * RS)      // one 128x32 fp16 tile in smem
#define STAGE_B (2 * TILE_B)   // A tile + B tile per stage
#define NSTAGE 3
#define MAXTILES 128

// ---- device scratch (static; no runtime allocation) ----
__device__ int   g_count[NE];
__device__ int   g_offset[NE];
__device__ int   g_cursor[NE];
__device__ int   g_tok[NPAIR];
__device__ float g_wgt[NPAIR];
__device__ int   g_slot[NPAIR];
__device__ int   g_tile_e[MAXTILES];
__device__ int   g_tile_m0[MAXTILES];
__device__ int   g_ntiles;

__device__ __half g_w1h[(size_t)NE * 2 * NI * NH];   // 67 MB
__device__ __half g_w2h[(size_t)NE * NH * NI];       // 33.5 MB
__device__ __half g_xh[(size_t)NT * NH];             // 4 MB
__device__ __half g_hh[(size_t)NPAIR * NI];          // 8 MB
__device__ float  g_part[(size_t)NPAIR * NH];        // 32 MB

// ===========================================================================
// asm helpers (baseline ISA only — compiles for plain sm_103)
// ===========================================================================
__device__ __forceinline__ uint32_t smem_u32(const void* p) {
    uint32_t a;
    asm("{ .reg .u64 t; cvta.to.shared.u64 t, %1; cvt.u32.u64 %0, t; }" : "=r"(a) : "l"(p));
    return a;
}
__device__ __forceinline__ void ldsm4(uint32_t* r, uint32_t a) {
    asm volatile("ldmatrix.sync.aligned.m8n8.x4.shared.b16 {%0,%1,%2,%3}, [%4];"
        : "=r"(r[0]), "=r"(r[1]), "=r"(r[2]), "=r"(r[3]) : "r"(a));
}
__device__ __forceinline__ void mma_fp16(float* d, const uint32_t* a, uint32_t b0, uint32_t b1) {
    asm volatile("mma.sync.aligned.m16n8k16.row.col.f32.f16.f16.f32 "
        "{%0,%1,%2,%3}, {%4,%5,%6,%7}, {%8,%9}, {%0,%1,%2,%3};"
        : "+f"(d[0]), "+f"(d[1]), "+f"(d[2]), "+f"(d[3])
        : "r"(a[0]), "r"(a[1]), "r"(a[2]), "r"(a[3]), "r"(b0), "r"(b1));
}
__device__ __forceinline__ void cp16(uint32_t dst, const void* src, int szbytes) {
    asm volatile("cp.async.cg.shared.global [%0], [%1], 16, %2;"
        :: "r"(dst), "l"(src), "r"(szbytes));
}
#define CP_COMMIT() asm volatile("cp.async.commit_group;" ::: "memory")
#define CP_WAIT(n)  asm volatile("cp.async.wait_group %0;" :: "n"(n) : "memory")

// ===========================================================================
// Setup kernels
// ===========================================================================
__global__ void k_init() {
    int i = threadIdx.x;
    if (i < NE) { g_count[i] = 0; g_cursor[i] = 0; }
}
__global__ void k_count(const int* __restrict__ idx) {
    int p = blockIdx.x * blockDim.x + threadIdx.x;
    if (p < NPAIR) atomicAdd(&g_count[idx[p]], 1);
}
__global__ void k_scan() {
    if (threadIdx.x == 0) {
        int acc = 0, nt = 0;
        for (int e = 0; e < NE; e++) {
            g_offset[e] = acc;
            for (int m0 = 0; m0 < g_count[e]; m0 += 128) {
                g_tile_e[nt] = e; g_tile_m0[nt] = m0; nt++;
            }
            acc += g_count[e];
        }
        g_ntiles = nt;
    }
}
__global__ void k_scatter(const int* __restrict__ idx, const float* __restrict__ w) {
    int p = blockIdx.x * blockDim.x + threadIdx.x;
    if (p < NPAIR) {
        int e = idx[p];
        int pos = g_offset[e] + atomicAdd(&g_cursor[e], 1);
        g_tok[pos] = p / NK;
        g_wgt[pos] = w[p];
        g_slot[p]  = pos;
    }
}

// fp32 -> fp16 round.  which: 0 = w1, 1 = w2, 2 = x
__global__ __launch_bounds__(256) void k_cvt(const float* __restrict__ src, int n8, int which) {
    int i = blockIdx.x * blockDim.x + threadIdx.x;
    if (i >= n8) return;
    __half* hi = (which == 0) ? g_w1h : (which == 1) ? g_w2h : g_xh;
    const float4* s = (const float4*)src + 2 * (size_t)i;
    float4 v0 = s[0], v1 = s[1];
    float f[8] = {v0.x, v0.y, v0.z, v0.w, v1.x, v1.y, v1.z, v1.w};
    unsigned hw[4];
    #pragma unroll
    for (int j = 0; j < 4; j++) {
        __half a = __float2half(f[2 * j]), b = __float2half(f[2 * j + 1]);
        hw[j] = (unsigned)__half_as_ushort(a) | ((unsigned)__half_as_ushort(b) << 16);
    }
    ((uint4*)hi)[i] = make_uint4(hw[0], hw[1], hw[2], hw[3]);
}

// ===========================================================================
// GEMM1: h = silu(x @ Wg^T) * (x @ Wu^T)
// 512 threads; tile M=128, gate 64 + up 64; K chunk 32; 3-stage cp.async.
// Stage: A (128x32) at +0, B (rows 0-63 gate, 64-127 up) at +TILE_B.
// Warp (16): wm=wid&3 -> M rows wm*32; wn=wid>>2 -> N16 block wn*16 of BOTH
// gate and up (so the silu epilogue is warp-local).
// ===========================================================================
__device__ __forceinline__ void g1_load(uint32_t sst, int k0, const int* s_tok,
                                        int e, int n0, int tid) {
    #pragma unroll
    for (int i = 0; i < 2; i++) {
        const int u = tid + i * 512;
        if (u < 512) {                               // A tile
            const int r = u >> 2, cu = u & 3;
            uint32_t dst = sst + (uint32_t)(r * RS + cu * 16);
            int tok = s_tok[r];
            const __half* src = (tok >= 0) ? g_xh + (size_t)tok * NH + k0 + cu * 8 : g_xh;
            cp16(dst, src, (tok >= 0) ? 16 : 0);
        } else {                                     // B tile
            const int v = u - 512;
            const int r = v >> 2, cu = v & 3;
            uint32_t dst = sst + (uint32_t)(TILE_B + r * RS + cu * 16);
            int row = (r < 64) ? (n0 + r) : (NI + n0 + (r - 64));
            cp16(dst, g_w1h + ((size_t)e * 2 * NI + row) * NH + k0 + cu * 8, 16);
        }
    }
}

__global__ __launch_bounds__(512, 1) void k_gemm1() {
    extern __shared__ char smdyn[];
    __shared__ int s_tok[128];
    const int tid = threadIdx.x, lane = tid & 31, wid = tid >> 5;
    const int wm = wid & 3, wn = wid >> 2;           // wn in 0..3
    const int grp = lane >> 3, lr = lane & 7;
    const int rowoff = ((grp & 1) << 3) + lr;
    const int csel = grp >> 1;
    const uint32_t sbase = smem_u32(smdyn);
    const int nwork = g_ntiles * 8;

    for (int w = blockIdx.x; w < nwork; w += gridDim.x) {
        const int mt = w >> 3, nt = w & 7;
        const int e = g_tile_e[mt], m0 = g_tile_m0[mt];
        const int cnt = g_count[e], seg = g_offset[e];
        const int n0 = nt * 64;

        if (tid < 128) s_tok[tid] = (m0 + tid < cnt) ? g_tok[seg + m0 + tid] : -1;
        __syncthreads();

        float cg[2][2][4], cup[2][2][4];
        #pragma unroll
        for (int i = 0; i < 2; i++)
            #pragma unroll
            for (int s = 0; s < 2; s++)
                #pragma unroll
                for (int q = 0; q < 4; q++) { cg[i][s][q] = 0.f; cup[i][s][q] = 0.f; }

        g1_load(sbase + 0 * STAGE_B, 0,  s_tok, e, n0, tid); CP_COMMIT();
        g1_load(sbase + 1 * STAGE_B, 32, s_tok, e, n0, tid); CP_COMMIT();
        #define G1_CHUNKS 32
        for (int c = 0; c < G1_CHUNKS; c++) {
            if (c + 2 < G1_CHUNKS) {
                g1_load(sbase + ((c + 2) % NSTAGE) * STAGE_B, (c + 2) * 32, s_tok, e, n0, tid);
                CP_COMMIT();
                CP_WAIT(2);
            } else if (c + 2 == G1_CHUNKS) {
                CP_WAIT(1);
            } else {
                CP_WAIT(0);
            }
            __syncthreads();
            {
                const uint32_t sst = sbase + (c % NSTAGE) * STAGE_B;
                const uint32_t uA = sst, uB = sst + TILE_B;
                #pragma unroll
                for (int kk = 0; kk < 2; kk++) {
                    const uint32_t kcoff = (uint32_t)((kk * 2 + csel) * 16);
                    uint32_t ah[2][4];
                    #pragma unroll
                    for (int i = 0; i < 2; i++)
                        ldsm4(ah[i], uA + (uint32_t)((wm * 32 + i * 16 + rowoff) * RS) + kcoff);
                    uint32_t bg[4], bu[4];
                    ldsm4(bg, uB + (uint32_t)((wn * 16 + rowoff) * RS) + kcoff);
                    ldsm4(bu, uB + (uint32_t)((64 + wn * 16 + rowoff) * RS) + kcoff);
                    #pragma unroll
                    for (int i = 0; i < 2; i++)
                        #pragma unroll
                        for (int s = 0; s < 2; s++) {
                            mma_fp16(cg[i][s],  ah[i], bg[s], bg[s + 2]);
                            mma_fp16(cup[i][s], ah[i], bu[s], bu[s + 2]);
                        }
                }
            }
            __syncthreads();
        }

        // epilogue: h = silu(gate)*up -> fp16, warp-local (gate & up both here)
        #pragma unroll
        for (int i = 0; i < 2; i++)
            #pragma unroll
            for (int h = 0; h < 2; h++) {
                int r = wm * 32 + i * 16 + h * 8 + (lane >> 2);
                int m = m0 + r;
                if (m < cnt) {
                    size_t rowb = (size_t)(seg + m) * NI + n0 + wn * 16 + 2 * (lane & 3);
                    #pragma unroll
                    for (int s = 0; s < 2; s++) {
                        float g0 = cg[i][s][2 * h], g1 = cg[i][s][2 * h + 1];
                        float u0 = cup[i][s][2 * h], u1 = cup[i][s][2 * h + 1];
                        float h0 = g0 / (1.0f + __expf(-g0)) * u0;
                        float h1 = g1 / (1.0f + __expf(-g1)) * u1;
                        __half p0 = __float2half(h0), p1 = __float2half(h1);
                        *(unsigned*)(g_hh + rowb + s * 8) =
                            (unsigned)__half_as_ushort(p0) | ((unsigned)__half_as_ushort(p1) << 16);
                    }
                }
            }
        __syncthreads();
    }
}

// ===========================================================================
// GEMM2: part = h @ W2^T; 512 threads; tile M=128, N=128; K chunk 32 (16)
// Warp: wm=wid&3 -> M rows wm*32; wn=wid>>2 -> N32 block wn*32.
// ===========================================================================
__device__ __forceinline__ void g2_load(uint32_t sst, int k0, int e, int n0,
                                        int seg, int m0, int cnt, int tid) {
    #pragma unroll
    for (int i = 0; i < 2; i++) {
        const int u = tid + i * 512;
        if (u < 512) {                               // A = h rows
            const int r = u >> 2, cu = u & 3;
            uint32_t dst = sst + (uint32_t)(r * RS + cu * 16);
            bool ok = (m0 + r < cnt);
            const __half* src = ok ? g_hh + (size_t)(seg + m0 + r) * NI + k0 + cu * 8 : g_hh;
            cp16(dst, src, ok ? 16 : 0);
        } else {                                     // B = w2 rows n0+r
            const int v = u - 512;
            const int r = v >> 2, cu = v & 3;
            uint32_t dst = sst + (uint32_t)(TILE_B + r * RS + cu * 16);
            cp16(dst, g_w2h + ((size_t)e * NH + n0 + r) * NI + k0 + cu * 8, 16);
        }
    }
}

__global__ __launch_bounds__(512, 1) void k_gemm2() {
    extern __shared__ char smdyn[];
    const int tid = threadIdx.x, lane = tid & 31, wid = tid >> 5;
    const int wm = wid & 3, wn = wid >> 2;
    const int grp = lane >> 3, lr = lane & 7;
    const int rowoff = ((grp & 1) << 3) + lr;
    const int csel = grp >> 1;
    const uint32_t sbase = smem_u32(smdyn);
    const int nwork = g_ntiles * 8;

    for (int w = blockIdx.x; w < nwork; w += gridDim.x) {
        const int mt = w >> 3, nt = w & 7;
        const int e = g_tile_e[mt], m0 = g_tile_m0[mt];
        const int cnt = g_count[e], seg = g_offset[e];
        const int n0 = nt * 128;

        float acc[2][4][4];
        #pragma unroll
        for (int i = 0; i < 2; i++)
            #pragma unroll
            for (int b = 0; b < 4; b++)
                #pragma unroll
                for (int q = 0; q < 4; q++) acc[i][b][q] = 0.f;

        g2_load(sbase + 0 * STAGE_B, 0,  e, n0, seg, m0, cnt, tid); CP_COMMIT();
        g2_load(sbase + 1 * STAGE_B, 32, e, n0, seg, m0, cnt, tid); CP_COMMIT();
        #define G2_CHUNKS 16
        for (int c = 0; c < G2_CHUNKS; c++) {
            if (c + 2 < G2_CHUNKS) {
                g2_load(sbase + ((c + 2) % NSTAGE) * STAGE_B, (c + 2) * 32, e, n0, seg, m0, cnt, tid);
                CP_COMMIT();
                CP_WAIT(2);
            } else if (c + 2 == G2_CHUNKS) {
                CP_WAIT(1);
            } else {
                CP_WAIT(0);
            }
            __syncthreads();
            {
                const uint32_t sst = sbase + (c % NSTAGE) * STAGE_B;
                const uint32_t uA = sst, uB = sst + TILE_B;
                #pragma unroll
                for (int kk = 0; kk < 2; kk++) {
                    const uint32_t kcoff = (uint32_t)((kk * 2 + csel) * 16);
                    uint32_t ah[2][4];
                    #pragma unroll
                    for (int i = 0; i < 2; i++)
                        ldsm4(ah[i], uA + (uint32_t)((wm * 32 + i * 16 + rowoff) * RS) + kcoff);
                    #pragma unroll
                    for (int t = 0; t < 2; t++) {
                        uint32_t bh[4];
                        ldsm4(bh, uB + (uint32_t)((wn * 32 + t * 16 + rowoff) * RS) + kcoff);
                        #pragma unroll
                        for (int i = 0; i < 2; i++)
                            #pragma unroll
                            for (int s = 0; s < 2; s++)
                                mma_fp16(acc[i][t * 2 + s], ah[i], bh[s], bh[s + 2]);
                    }
                }
            }
            __syncthreads();
        }

        #pragma unroll
        for (int i = 0; i < 2; i++)
            #pragma unroll
            for (int h = 0; h < 2; h++) {
                int r = wm * 32 + i * 16 + h * 8 + (lane >> 2);
                int m = m0 + r;
                if (m < cnt) {
                    float* dst = g_part + (size_t)(seg + m) * NH + n0 + wn * 32 + 2 * (lane & 3);
                    #pragma unroll
                    for (int b = 0; b < 4; b++)
                        *(float2*)(dst + b * 8) = make_float2(acc[i][b][2 * h], acc[i][b][2 * h + 1]);
                }
            }
    }
}

// ===========================================================================
// Reduce: out[t] = sum_k w[slot(t,k)] * part[slot(t,k)]  (deterministic order)
// ===========================================================================
__global__ void k_reduce(float* __restrict__ out) {
    const int t  = blockIdx.y;
    const int h4 = threadIdx.x;
    float4 acc = make_float4(0.f, 0.f, 0.f, 0.f);
    #pragma unroll
    for (int k = 0; k < NK; k++) {
        int s = g_slot[t * NK + k];
        float w = g_wgt[s];
        float4 v = *(const float4*)(g_part + (size_t)s * NH + h4 * 4);
        acc.x += w * v.x; acc.y += w * v.y; acc.z += w * v.z; acc.w += w * v.w;
    }
    *(float4*)(out + (size_t)t * NH + h4 * 4) = acc;
}

// ===========================================================================
extern "C" void kernel_launch(void* const* d_in, const int* in_sizes, int n_in,
                              void* d_out, int out_size) {
    const float* x   = (const float*)d_in[0];   // hidden_states  [T,H]
    const int*   idx = (const int*)d_in[1];     // top_k_index    [T,K]
    const float* tw  = (const float*)d_in[2];   // top_k_weights  [T,K]
    const float* w1  = (const float*)d_in[3];   // gate_up_proj   [E,2I,H]
    const float* w2  = (const float*)d_in[4];   // down_proj      [E,H,I]
    float* out = (float*)d_out;                 // [T,H] fp32
    (void)in_sizes; (void)n_in; (void)out_size;

    cudaFuncSetAttribute(k_gemm1, cudaFuncAttributeMaxDynamicSharedMemorySize, NSTAGE * STAGE_B);
    cudaFuncSetAttribute(k_gemm2, cudaFuncAttributeMaxDynamicSharedMemorySize, NSTAGE * STAGE_B);

    k_init<<<1, 32>>>();
    k_count<<<(NPAIR + 255) / 256, 256>>>(idx);
    k_scan<<<1, 32>>>();
    k_scatter<<<(NPAIR + 255) / 256, 256>>>(idx, tw);

    // convert to fp16 (round)
    k_cvt<<<(NE * 2 * NI * NH / 8 + 255) / 256, 256>>>(w1, NE * 2 * NI * NH / 8, 0);
    k_cvt<<<(NE * NH * NI / 8 + 255) / 256, 256>>>(w2, NE * NH * NI / 8, 1);
    k_cvt<<<(NT * NH / 8 + 255) / 256, 256>>>(x, NT * NH / 8, 2);

    k_gemm1<<<148, 512, NSTAGE * STAGE_B>>>();
    k_gemm2<<<148, 512, NSTAGE * STAGE_B>>>();
    k_reduce<<<dim3(1, NT), 256>>>(out);
}

// round 12
// speedup vs baseline: 3.6701x; 1.1108x over previous
#include <cuda_runtime.h>
#include <cuda_fp16.h>
#include <cstdint>

// Problem dims (fixed by the reference).
#define NE 32
#define NT 2048
#define NH 1024
#define NI 512
#define NK 4
#define NPAIR (NT * NK)        // 8192 (token, expert) pairs
#define RS 144                 // smem row stride: 64 fp16 (128B) + 16B pad (conflict-free ldsm)
#define TILE_B (128 * RS)      // one 128x64 fp16 tile in smem (18432 B)
#define STAGE_B (2 * TILE_B)   // A tile + B tile per stage (36864 B)
#define NSTAGE 3
#define MAXTILES 128

// ---- device scratch (static; no runtime allocation) ----
__device__ int   g_count[NE];
__device__ int   g_offset[NE];
__device__ int   g_cursor[NE];
__device__ int   g_tok[NPAIR];
__device__ float g_wgt[NPAIR];
__device__ int   g_slot[NPAIR];
__device__ int   g_tile_e[MAXTILES];
__device__ int   g_tile_m0[MAXTILES];
__device__ int   g_ntiles;

__device__ __half g_w1h[(size_t)NE * 2 * NI * NH];   // 67 MB
__device__ __half g_w2h[(size_t)NE * NH * NI];       // 33.5 MB
__device__ __half g_xh[(size_t)NT * NH];             // 4 MB
__device__ __half g_hh[(size_t)NPAIR * NI];          // 8 MB
__device__ float  g_part[(size_t)NPAIR * NH];        // 32 MB

// ===========================================================================
// asm helpers (baseline ISA only — compiles for plain sm_103)
// ===========================================================================
__device__ __forceinline__ uint32_t smem_u32(const void* p) {
    uint32_t a;
    asm("{ .reg .u64 t; cvta.to.shared.u64 t, %1; cvt.u32.u64 %0, t; }" : "=r"(a) : "l"(p));
    return a;
}
__device__ __forceinline__ void ldsm4(uint32_t* r, uint32_t a) {
    asm volatile("ldmatrix.sync.aligned.m8n8.x4.shared.b16 {%0,%1,%2,%3}, [%4];"
        : "=r"(r[0]), "=r"(r[1]), "=r"(r[2]), "=r"(r[3]) : "r"(a));
}
__device__ __forceinline__ void mma_fp16(float* d, const uint32_t* a, uint32_t b0, uint32_t b1) {
    asm volatile("mma.sync.aligned.m16n8k16.row.col.f32.f16.f16.f32 "
        "{%0,%1,%2,%3}, {%4,%5,%6,%7}, {%8,%9}, {%0,%1,%2,%3};"
        : "+f"(d[0]), "+f"(d[1]), "+f"(d[2]), "+f"(d[3])
        : "r"(a[0]), "r"(a[1]), "r"(a[2]), "r"(a[3]), "r"(b0), "r"(b1));
}
__device__ __forceinline__ void cp16(uint32_t dst, const void* src, int szbytes) {
    asm volatile("cp.async.cg.shared.global [%0], [%1], 16, %2;"
        :: "r"(dst), "l"(src), "r"(szbytes));
}
#define CP_COMMIT() asm volatile("cp.async.commit_group;" ::: "memory")
#define CP_WAIT(n)  asm volatile("cp.async.wait_group %0;" :: "n"(n) : "memory")

// ===========================================================================
// Setup kernels
// ===========================================================================
__global__ void k_init() {
    int i = threadIdx.x;
    if (i < NE) { g_count[i] = 0; g_cursor[i] = 0; }
}
__global__ void k_count(const int* __restrict__ idx) {
    int p = blockIdx.x * blockDim.x + threadIdx.x;
    if (p < NPAIR) atomicAdd(&g_count[idx[p]], 1);
}
__global__ void k_scan() {
    if (threadIdx.x == 0) {
        int acc = 0, nt = 0;
        for (int e = 0; e < NE; e++) {
            g_offset[e] = acc;
            for (int m0 = 0; m0 < g_count[e]; m0 += 128) {
                g_tile_e[nt] = e; g_tile_m0[nt] = m0; nt++;
            }
            acc += g_count[e];
        }
        g_ntiles = nt;
    }
}
__global__ void k_scatter(const int* __restrict__ idx, const float* __restrict__ w) {
    int p = blockIdx.x * blockDim.x + threadIdx.x;
    if (p < NPAIR) {
        int e = idx[p];
        int pos = g_offset[e] + atomicAdd(&g_cursor[e], 1);
        g_tok[pos] = p / NK;
        g_wgt[pos] = w[p];
        g_slot[p]  = pos;
    }
}

// fp32 -> fp16 round.  which: 0 = w1, 1 = w2, 2 = x
__global__ __launch_bounds__(256) void k_cvt(const float* __restrict__ src, int n8, int which) {
    int i = blockIdx.x * blockDim.x + threadIdx.x;
    if (i >= n8) return;
    __half* hi = (which == 0) ? g_w1h : (which == 1) ? g_w2h : g_xh;
    const float4* s = (const float4*)src + 2 * (size_t)i;
    float4 v0 = s[0], v1 = s[1];
    float f[8] = {v0.x, v0.y, v0.z, v0.w, v1.x, v1.y, v1.z, v1.w};
    unsigned hw[4];
    #pragma unroll
    for (int j = 0; j < 4; j++) {
        __half a = __float2half(f[2 * j]), b = __float2half(f[2 * j + 1]);
        hw[j] = (unsigned)__half_as_ushort(a) | ((unsigned)__half_as_ushort(b) << 16);
    }
    ((uint4*)hi)[i] = make_uint4(hw[0], hw[1], hw[2], hw[3]);
}

// ===========================================================================
// GEMM1: h = silu(x @ Wg^T) * (x @ Wu^T)
// 512 threads; tile M=128, gate 64 + up 64; K chunk 64; 3-stage cp.async.
// Stage: A (128x64) at +0, B (rows 0-63 gate, 64-127 up) at +TILE_B.
// Warp (16): wm=wid&3 -> M rows wm*32; wn=wid>>2 -> N16 block wn*16 of BOTH
// gate and up (so the silu epilogue is warp-local).
// ===========================================================================
__device__ __forceinline__ void g1_load(uint32_t sst, int k0, const int* s_tok,
                                        int e, int n0, int tid) {
    #pragma unroll
    for (int i = 0; i < 4; i++) {
        const int u = tid + i * 512;                 // 0..2047
        if (u < 1024) {                              // A tile: 128 rows x 8 units
            const int r = u >> 3, cu = u & 7;
            uint32_t dst = sst + (uint32_t)(r * RS + cu * 16);
            int tok = s_tok[r];
            const __half* src = (tok >= 0) ? g_xh + (size_t)tok * NH + k0 + cu * 8 : g_xh;
            cp16(dst, src, (tok >= 0) ? 16 : 0);
        } else {                                     // B tile
            const int v = u - 1024;
            const int r = v >> 3, cu = v & 7;
            uint32_t dst = sst + (uint32_t)(TILE_B + r * RS + cu * 16);
            int row = (r < 64) ? (n0 + r) : (NI + n0 + (r - 64));
            cp16(dst, g_w1h + ((size_t)e * 2 * NI + row) * NH + k0 + cu * 8, 16);
        }
    }
}

__global__ __launch_bounds__(512, 1) void k_gemm1() {
    extern __shared__ char smdyn[];
    __shared__ int s_tok[128];
    const int tid = threadIdx.x, lane = tid & 31, wid = tid >> 5;
    const int wm = wid & 3, wn = wid >> 2;           // wn in 0..3
    const int grp = lane >> 3, lr = lane & 7;
    const int rowoff = ((grp & 1) << 3) + lr;
    const int csel = grp >> 1;
    const uint32_t sbase = smem_u32(smdyn);
    const int nwork = g_ntiles * 8;

    for (int w = blockIdx.x; w < nwork; w += gridDim.x) {
        const int mt = w >> 3, nt = w & 7;
        const int e = g_tile_e[mt], m0 = g_tile_m0[mt];
        const int cnt = g_count[e], seg = g_offset[e];
        const int n0 = nt * 64;

        if (tid < 128) s_tok[tid] = (m0 + tid < cnt) ? g_tok[seg + m0 + tid] : -1;
        __syncthreads();

        float cg[2][2][4], cup[2][2][4];
        #pragma unroll
        for (int i = 0; i < 2; i++)
            #pragma unroll
            for (int s = 0; s < 2; s++)
                #pragma unroll
                for (int q = 0; q < 4; q++) { cg[i][s][q] = 0.f; cup[i][s][q] = 0.f; }

        g1_load(sbase + 0 * STAGE_B, 0,  s_tok, e, n0, tid); CP_COMMIT();
        g1_load(sbase + 1 * STAGE_B, 64, s_tok, e, n0, tid); CP_COMMIT();
        #define G1_CHUNKS 16
        for (int c = 0; c < G1_CHUNKS; c++) {
            if (c + 2 < G1_CHUNKS) {
                g1_load(sbase + ((c + 2) % NSTAGE) * STAGE_B, (c + 2) * 64, s_tok, e, n0, tid);
                CP_COMMIT();
                CP_WAIT(2);
            } else if (c + 2 == G1_CHUNKS) {
                CP_WAIT(1);
            } else {
                CP_WAIT(0);
            }
            __syncthreads();
            {
                const uint32_t sst = sbase + (c % NSTAGE) * STAGE_B;
                const uint32_t uA = sst, uB = sst + TILE_B;
                #pragma unroll
                for (int kk = 0; kk < 4; kk++) {
                    const uint32_t kcoff = (uint32_t)((kk * 2 + csel) * 16);
                    uint32_t ah[2][4];
                    #pragma unroll
                    for (int i = 0; i < 2; i++)
                        ldsm4(ah[i], uA + (uint32_t)((wm * 32 + i * 16 + rowoff) * RS) + kcoff);
                    uint32_t bg[4], bu[4];
                    ldsm4(bg, uB + (uint32_t)((wn * 16 + rowoff) * RS) + kcoff);
                    ldsm4(bu, uB + (uint32_t)((64 + wn * 16 + rowoff) * RS) + kcoff);
                    #pragma unroll
                    for (int i = 0; i < 2; i++)
                        #pragma unroll
                        for (int s = 0; s < 2; s++) {
                            mma_fp16(cg[i][s],  ah[i], bg[s], bg[s + 2]);
                            mma_fp16(cup[i][s], ah[i], bu[s], bu[s + 2]);
                        }
                }
            }
            __syncthreads();
        }

        // epilogue: h = silu(gate)*up -> fp16, warp-local (gate & up both here)
        #pragma unroll
        for (int i = 0; i < 2; i++)
            #pragma unroll
            for (int h = 0; h < 2; h++) {
                int r = wm * 32 + i * 16 + h * 8 + (lane >> 2);
                int m = m0 + r;
                if (m < cnt) {
                    size_t rowb = (size_t)(seg + m) * NI + n0 + wn * 16 + 2 * (lane & 3);
                    #pragma unroll
                    for (int s = 0; s < 2; s++) {
                        float g0 = cg[i][s][2 * h], g1 = cg[i][s][2 * h + 1];
                        float u0 = cup[i][s][2 * h], u1 = cup[i][s][2 * h + 1];
                        float h0 = g0 / (1.0f + __expf(-g0)) * u0;
                        float h1 = g1 / (1.0f + __expf(-g1)) * u1;
                        __half p0 = __float2half(h0), p1 = __float2half(h1);
                        *(unsigned*)(g_hh + rowb + s * 8) =
                            (unsigned)__half_as_ushort(p0) | ((unsigned)__half_as_ushort(p1) << 16);
                    }
                }
            }
        __syncthreads();
    }
}

// ===========================================================================
// GEMM2: part = h @ W2^T; 512 threads; tile M=128, N=128; K chunk 64 (8)
// Warp: wm=wid&3 -> M rows wm*32; wn=wid>>2 -> N32 block wn*32.
// ===========================================================================
__device__ __forceinline__ void g2_load(uint32_t sst, int k0, int e, int n0,
                                        int seg, int m0, int cnt, int tid) {
    #pragma unroll
    for (int i = 0; i < 4; i++) {
        const int u = tid + i * 512;
        if (u < 1024) {                              // A = h rows
            const int r = u >> 3, cu = u & 7;
            uint32_t dst = sst + (uint32_t)(r * RS + cu * 16);
            bool ok = (m0 + r < cnt);
            const __half* src = ok ? g_hh + (size_t)(seg + m0 + r) * NI + k0 + cu * 8 : g_hh;
            cp16(dst, src, ok ? 16 : 0);
        } else {                                     // B = w2 rows n0+r
            const int v = u - 1024;
            const int r = v >> 3, cu = v & 7;
            uint32_t dst = sst + (uint32_t)(TILE_B + r * RS + cu * 16);
            cp16(dst, g_w2h + ((size_t)e * NH + n0 + r) * NI + k0 + cu * 8, 16);
        }
    }
}

__global__ __launch_bounds__(512, 1) void k_gemm2() {
    extern __shared__ char smdyn[];
    const int tid = threadIdx.x, lane = tid & 31, wid = tid >> 5;
    const int wm = wid & 3, wn = wid >> 2;
    const int grp = lane >> 3, lr = lane & 7;
    const int rowoff = ((grp & 1) << 3) + lr;
    const int csel = grp >> 1;
    const uint32_t sbase = smem_u32(smdyn);
    const int nwork = g_ntiles * 8;

    for (int w = blockIdx.x; w < nwork; w += gridDim.x) {
        const int mt = w >> 3, nt = w & 7;
        const int e = g_tile_e[mt], m0 = g_tile_m0[mt];
        const int cnt = g_count[e], seg = g_offset[e];
        const int n0 = nt * 128;

        float acc[2][4][4];
        #pragma unroll
        for (int i = 0; i < 2; i++)
            #pragma unroll
            for (int b = 0; b < 4; b++)
                #pragma unroll
                for (int q = 0; q < 4; q++) acc[i][b][q] = 0.f;

        g2_load(sbase + 0 * STAGE_B, 0,  e, n0, seg, m0, cnt, tid); CP_COMMIT();
        g2_load(sbase + 1 * STAGE_B, 64, e, n0, seg, m0, cnt, tid); CP_COMMIT();
        #define G2_CHUNKS 8
        for (int c = 0; c < G2_CHUNKS; c++) {
            if (c + 2 < G2_CHUNKS) {
                g2_load(sbase + ((c + 2) % NSTAGE) * STAGE_B, (c + 2) * 64, e, n0, seg, m0, cnt, tid);
                CP_COMMIT();
                CP_WAIT(2);
            } else if (c + 2 == G2_CHUNKS) {
                CP_WAIT(1);
            } else {
                CP_WAIT(0);
            }
            __syncthreads();
            {
                const uint32_t sst = sbase + (c % NSTAGE) * STAGE_B;
                const uint32_t uA = sst, uB = sst + TILE_B;
                #pragma unroll
                for (int kk = 0; kk < 4; kk++) {
                    const uint32_t kcoff = (uint32_t)((kk * 2 + csel) * 16);
                    uint32_t ah[2][4];
                    #pragma unroll
                    for (int i = 0; i < 2; i++)
                        ldsm4(ah[i], uA + (uint32_t)((wm * 32 + i * 16 + rowoff) * RS) + kcoff);
                    #pragma unroll
                    for (int t = 0; t < 2; t++) {
                        uint32_t bh[4];
                        ldsm4(bh, uB + (uint32_t)((wn * 32 + t * 16 + rowoff) * RS) + kcoff);
                        #pragma unroll
                        for (int i = 0; i < 2; i++)
                            #pragma unroll
                            for (int s = 0; s < 2; s++)
                                mma_fp16(acc[i][t * 2 + s], ah[i], bh[s], bh[s + 2]);
                    }
                }
            }
            __syncthreads();
        }

        #pragma unroll
        for (int i = 0; i < 2; i++)
            #pragma unroll
            for (int h = 0; h < 2; h++) {
                int r = wm * 32 + i * 16 + h * 8 + (lane >> 2);
                int m = m0 + r;
                if (m < cnt) {
                    float* dst = g_part + (size_t)(seg + m) * NH + n0 + wn * 32 + 2 * (lane & 3);
                    #pragma unroll
                    for (int b = 0; b < 4; b++)
                        *(float2*)(dst + b * 8) = make_float2(acc[i][b][2 * h], acc[i][b][2 * h + 1]);
                }
            }
    }
}

// ===========================================================================
// Reduce: out[t] = sum_k w[slot(t,k)] * part[slot(t,k)]  (deterministic order)
// ===========================================================================
__global__ void k_reduce(float* __restrict__ out) {
    const int t  = blockIdx.y;
    const int h4 = threadIdx.x;
    float4 acc = make_float4(0.f, 0.f, 0.f, 0.f);
    #pragma unroll
    for (int k = 0; k < NK; k++) {
        int s = g_slot[t * NK + k];
        float w = g_wgt[s];
        float4 v = *(const float4*)(g_part + (size_t)s * NH + h4 * 4);
        acc.x += w * v.x; acc.y += w * v.y; acc.z += w * v.z; acc.w += w * v.w;
    }
    *(float4*)(out + (size_t)t * NH + h4 * 4) = acc;
}

// ===========================================================================
extern "C" void kernel_launch(void* const* d_in, const int* in_sizes, int n_in,
                              void* d_out, int out_size) {
    const float* x   = (const float*)d_in[0];   // hidden_states  [T,H]
    const int*   idx = (const int*)d_in[1];     // top_k_index    [T,K]
    const float* tw  = (const float*)d_in[2];   // top_k_weights  [T,K]
    const float* w1  = (const float*)d_in[3];   // gate_up_proj   [E,2I,H]
    const float* w2  = (const float*)d_in[4];   // down_proj      [E,H,I]
    float* out = (float*)d_out;                 // [T,H] fp32
    (void)in_sizes; (void)n_in; (void)out_size;

    cudaFuncSetAttribute(k_gemm1, cudaFuncAttributeMaxDynamicSharedMemorySize, NSTAGE * STAGE_B);
    cudaFuncSetAttribute(k_gemm2, cudaFuncAttributeMaxDynamicSharedMemorySize, NSTAGE * STAGE_B);

    k_init<<<1, 32>>>();
    k_count<<<(NPAIR + 255) / 256, 256>>>(idx);
    k_scan<<<1, 32>>>();
    k_scatter<<<(NPAIR + 255) / 256, 256>>>(idx, tw);

    // convert to fp16 (round)
    k_cvt<<<(NE * 2 * NI * NH / 8 + 255) / 256, 256>>>(w1, NE * 2 * NI * NH / 8, 0);
    k_cvt<<<(NE * NH * NI / 8 + 255) / 256, 256>>>(w2, NE * NH * NI / 8, 1);
    k_cvt<<<(NT * NH / 8 + 255) / 256, 256>>>(x, NT * NH / 8, 2);

    k_gemm1<<<148, 512, NSTAGE * STAGE_B>>>();
    k_gemm2<<<148, 512, NSTAGE * STAGE_B>>>();
    k_reduce<<<dim3(1, NT), 256>>>(out);
}